// round 6
// baseline (speedup 1.0000x reference)
#include <cuda_runtime.h>
#include <cuda_fp16.h>
#include <cstdint>

#define NTOK 512
#define CDIM 128
#define LLOC 144
#define DDIM 256
#define FSTRIDE (LLOC * CDIM)
#define SKB 272     // fp16 temp row stride (bytes)
#define RS  144     // s8 row stride (bytes)

// smem byte offsets
#define OFF_T    0                    // loc fp16: 128*272 = 34816
#define OFF_W2   34816                // W2 fp16 tile: 64*272 = 17408
#define OFF_A1   52224                // preds1 s8: 128*144
#define OFF_A2   70656                // preds2 s8: 128*144
#define OFF_B0   89088                // pos s8 buf0: 64*144
#define OFF_B1   98304                // pos s8 buf1
#define OFF_SB   107520               // 2*64 floats (B row scales)
#define OFF_RM   108032               // 128 floats (A2 row max)
#define OFF_ROWS 108544               // 256 floats
#define OFF_WRED 109568               // 8 floats
#define SMEM_TOTAL 109600

__device__ int8_t g_p1q[NTOK * CDIM];
__device__ float  g_sA1[NTOK];
__device__ double g_acc;

// preds1 = f_t@W1^T + b1, quantized per-row to int8 with exact row max
__global__ void preds1_k(const float* __restrict__ f_t,
                         const float* __restrict__ W1,
                         const float* __restrict__ b1) {
    __shared__ float fr[DDIM];
    __shared__ float wmax[4];
    const int n = blockIdx.x;
    const int c = threadIdx.x;   // 128 threads
    if (n == 0 && c == 0) g_acc = 0.0;
    fr[c]       = f_t[n * DDIM + c];
    fr[c + 128] = f_t[n * DDIM + c + 128];
    __syncthreads();
    float s = b1[c];
    const float* w = W1 + c * DDIM;
#pragma unroll 8
    for (int k = 0; k < DDIM; ++k) s = fmaf(fr[k], w[k], s);
    float m = fabsf(s);
#pragma unroll
    for (int off = 16; off > 0; off >>= 1)
        m = fmaxf(m, __shfl_xor_sync(0xffffffffu, m, off));
    if ((c & 31) == 0) wmax[c >> 5] = m;
    __syncthreads();
    float mm = fmaxf(fmaxf(wmax[0], wmax[1]), fmaxf(wmax[2], wmax[3]));
    g_p1q[n * CDIM + c] = (int8_t)__float2int_rn(s * (127.0f / mm));
    if (c == 0) g_sA1[n] = mm * (1.0f / 127.0f);
}

__global__ void final_k(float* __restrict__ out) {
    out[0] = (float)(g_acc / (double)(LLOC * NTOK));
}

__device__ __forceinline__ uint32_t ph2(float x, float y) {
    __half2 h = __floats2half2_rn(x, y);
    return *reinterpret_cast<uint32_t*>(&h);
}
__device__ __forceinline__ float2 up2(uint32_t v) {
    return __half22float2(*reinterpret_cast<__half2*>(&v));
}
__device__ __forceinline__ void stage8h(char* tile, int row, int k0,
                                        const float* __restrict__ src) {
    float4 a = *reinterpret_cast<const float4*>(src);
    float4 b = *reinterpret_cast<const float4*>(src + 4);
    uint4 v;
    v.x = ph2(a.x, a.y); v.y = ph2(a.z, a.w);
    v.z = ph2(b.x, b.y); v.w = ph2(b.z, b.w);
    *reinterpret_cast<uint4*>(tile + row * SKB + k0 * 2) = v;
}
__device__ __forceinline__ uint32_t pack4(float4 v, float inv) {
    int q0 = __float2int_rn(v.x * inv), q1 = __float2int_rn(v.y * inv);
    int q2 = __float2int_rn(v.z * inv), q3 = __float2int_rn(v.w * inv);
    return (q0 & 0xFF) | ((q1 & 0xFF) << 8) | ((q2 & 0xFF) << 16) | ((q3 & 0xFF) << 24);
}

#define LDSM4(r0, r1, r2, r3, addr) \
    asm volatile("ldmatrix.sync.aligned.m8n8.x4.shared.b16 {%0,%1,%2,%3}, [%4];" \
                 : "=r"(r0), "=r"(r1), "=r"(r2), "=r"(r3) : "r"(addr))

__device__ __forceinline__ void mma16h(uint32_t* c, const uint32_t* a, const uint32_t* b) {
    asm volatile(
        "mma.sync.aligned.m16n8k16.row.col.f16.f16.f16.f16 "
        "{%0,%1}, {%2,%3,%4,%5}, {%6,%7}, {%0,%1};\n"
        : "+r"(c[0]), "+r"(c[1])
        : "r"(a[0]), "r"(a[1]), "r"(a[2]), "r"(a[3]), "r"(b[0]), "r"(b[1]));
}
__device__ __forceinline__ void mma32s8(int* c, const uint32_t* a, const uint32_t* b) {
    asm volatile(
        "mma.sync.aligned.m16n8k32.row.col.s32.s8.s8.s32 "
        "{%0,%1,%2,%3}, {%4,%5,%6,%7}, {%8,%9}, {%0,%1,%2,%3};\n"
        : "+r"(c[0]), "+r"(c[1]), "+r"(c[2]), "+r"(c[3])
        : "r"(a[0]), "r"(a[1]), "r"(a[2]), "r"(a[3]), "r"(b[0]), "r"(b[1]));
}

__global__ void __launch_bounds__(256, 1)
main_k(const float* __restrict__ fmap_t,
       const float* __restrict__ fmap_tp1,
       const float* __restrict__ W2,
       const float* __restrict__ b2) {
    extern __shared__ char sm[];
    const uint32_t sbase = (uint32_t)__cvta_generic_to_shared(sm);
    float* sB   = reinterpret_cast<float*>(sm + OFF_SB);
    float* rm   = reinterpret_cast<float*>(sm + OFF_RM);
    float* rowS = reinterpret_cast<float*>(sm + OFF_ROWS);
    float* wred = reinterpret_cast<float*>(sm + OFF_WRED);

    const int l    = blockIdx.y;
    const int nb   = blockIdx.x;
    const int t    = threadIdx.x;
    const int lane = t & 31, warp = t >> 5;
    const int wy   = warp >> 1, wx = warp & 1;
    const int g    = lane >> 2, tig = lane & 3;

    // fp16 ldmatrix lane addressing (prologue, half-element offsets)
    const uint32_t aRowH = lane & 15, aKoffH = ((lane >> 4) << 3);
    const uint32_t bRowH = ((lane >> 4) << 3) + (lane & 7), bKoffH = (((lane >> 3) & 1) << 3);
    // s8 ldmatrix lane addressing (byte offsets)
    const uint32_t aRowQ = lane & 15, aKoffQ = ((lane >> 4) << 4);
    const uint32_t bRowQ = bRowH,      bKoffQ = (((lane >> 3) & 1) << 4);

    // ---------------- Phase 0 ----------------
    {
        int row = t >> 1, half = t & 1;
        const uint4* s1 = reinterpret_cast<const uint4*>(
            g_p1q + (size_t)(nb * 128 + row) * CDIM + half * 64);
        uint4* d1 = reinterpret_cast<uint4*>(sm + OFF_A1 + row * RS + half * 64);
#pragma unroll
        for (int j = 0; j < 4; ++j) d1[j] = s1[j];
        const float4* s2 = reinterpret_cast<const float4*>(
            fmap_t + (size_t)(nb * 128 + row) * FSTRIDE + l * CDIM) + half * 16;
        uint4* d2 = reinterpret_cast<uint4*>(sm + OFF_T + row * SKB + half * 128);
#pragma unroll
        for (int j = 0; j < 8; ++j) {
            float4 a = s2[2 * j], b = s2[2 * j + 1];
            uint4 v;
            v.x = ph2(a.x, a.y); v.y = ph2(a.z, a.w);
            v.z = ph2(b.x, b.y); v.w = ph2(b.z, b.w);
            d2[j] = v;
        }
    }
    rowS[t] = 0.f;
    if (t < 128) rm[t] = 0.f;
    __syncthreads();

    // ---------------- Phase 1: preds2 = loc @ W2^T + b2 (fp16) ----------------
    uint32_t pc[2][2][4][2];
#pragma unroll
    for (int p = 0; p < 2; ++p)
#pragma unroll
        for (int mi = 0; mi < 2; ++mi)
#pragma unroll
            for (int ni = 0; ni < 4; ++ni) { pc[p][mi][ni][0] = 0u; pc[p][mi][ni][1] = 0u; }

#pragma unroll 1
    for (int p = 0; p < 2; ++p) {
        if (p) __syncthreads();
        {
            int row = t >> 2, k0 = (t & 3) * 32;
            const float* src = W2 + (size_t)(p * 64 + row) * CDIM + k0;
#pragma unroll
            for (int j = 0; j < 4; ++j) stage8h(sm + OFF_W2, row, k0 + j * 8, src + j * 8);
        }
        __syncthreads();
#pragma unroll
        for (int ks = 0; ks < 8; ++ks) {
            const int k0 = ks * 16;
            uint32_t a[2][4], b[4][2];
#pragma unroll
            for (int mi = 0; mi < 2; ++mi) {
                uint32_t ad = sbase + OFF_T + (wy * 32 + mi * 16 + aRowH) * SKB
                            + (k0 + aKoffH) * 2;
                LDSM4(a[mi][0], a[mi][1], a[mi][2], a[mi][3], ad);
            }
#pragma unroll
            for (int nt = 0; nt < 2; ++nt) {
                uint32_t bd = sbase + OFF_W2 + (wx * 32 + nt * 16 + bRowH) * SKB
                            + (k0 + bKoffH) * 2;
                LDSM4(b[nt * 2][0], b[nt * 2][1], b[nt * 2 + 1][0], b[nt * 2 + 1][1], bd);
            }
#pragma unroll
            for (int mi = 0; mi < 2; ++mi)
#pragma unroll
                for (int ni = 0; ni < 4; ++ni) mma16h(pc[p][mi][ni], a[mi], b[ni]);
        }
    }
    __syncthreads();

    // preds2 epilogue: +b2, track per-row max, stash fp16 pairs back into pc
    float mrow[4] = {0.f, 0.f, 0.f, 0.f};
#pragma unroll
    for (int p = 0; p < 2; ++p)
#pragma unroll
        for (int mi = 0; mi < 2; ++mi)
#pragma unroll
            for (int ni = 0; ni < 4; ++ni) {
                int col = p * 64 + wx * 32 + ni * 8 + tig * 2;
                float bv0 = __ldg(b2 + col), bv1 = __ldg(b2 + col + 1);
                float2 lo = up2(pc[p][mi][ni][0]), hi = up2(pc[p][mi][ni][1]);
                float v00 = lo.x + bv0, v01 = lo.y + bv1;
                float v10 = hi.x + bv0, v11 = hi.y + bv1;
                mrow[mi * 2 + 0] = fmaxf(mrow[mi * 2 + 0], fmaxf(fabsf(v00), fabsf(v01)));
                mrow[mi * 2 + 1] = fmaxf(mrow[mi * 2 + 1], fmaxf(fabsf(v10), fabsf(v11)));
                pc[p][mi][ni][0] = ph2(v00, v01);
                pc[p][mi][ni][1] = ph2(v10, v11);
            }
#pragma unroll
    for (int mi = 0; mi < 2; ++mi)
#pragma unroll
        for (int h = 0; h < 2; ++h) {
            int r = wy * 32 + mi * 16 + g + h * 8;
            atomicMax(reinterpret_cast<int*>(&rm[r]), __float_as_int(mrow[mi * 2 + h]));
        }
    __syncthreads();

    float sa1v[4], sa2v[4], invr[4];
#pragma unroll
    for (int mi = 0; mi < 2; ++mi)
#pragma unroll
        for (int h = 0; h < 2; ++h) {
            int r = wy * 32 + mi * 16 + g + h * 8;
            float m = rm[r];
            invr[mi * 2 + h] = (m > 0.f) ? 127.0f / m : 0.f;
            sa2v[mi * 2 + h] = m * (1.0f / 127.0f);
            sa1v[mi * 2 + h] = g_sA1[nb * 128 + r];
        }
    // quantize preds2 into A2 (s8)
#pragma unroll
    for (int p = 0; p < 2; ++p)
#pragma unroll
        for (int mi = 0; mi < 2; ++mi)
#pragma unroll
            for (int ni = 0; ni < 4; ++ni) {
                int col = p * 64 + wx * 32 + ni * 8 + tig * 2;
                int r0 = wy * 32 + mi * 16 + g;
                float2 lo = up2(pc[p][mi][ni][0]), hi = up2(pc[p][mi][ni][1]);
                int q0 = __float2int_rn(lo.x * invr[mi * 2]);
                int q1 = __float2int_rn(lo.y * invr[mi * 2]);
                int q2 = __float2int_rn(hi.x * invr[mi * 2 + 1]);
                int q3 = __float2int_rn(hi.y * invr[mi * 2 + 1]);
                *reinterpret_cast<uint16_t*>(sm + OFF_A2 + r0 * RS + col) =
                    (uint16_t)((q0 & 0xFF) | ((q1 & 0xFF) << 8));
                *reinterpret_cast<uint16_t*>(sm + OFF_A2 + (r0 + 8) * RS + col) =
                    (uint16_t)((q2 & 0xFF) | ((q3 & 0xFF) << 8));
            }
    __syncthreads();

    // ---------------- Phase 2: main loop, 8 chunks of 64 pos tokens ----------------
    float S1[4] = {0.f, 0.f, 0.f, 0.f};
    float S2[4] = {0.f, 0.f, 0.f, 0.f};
    float diagAcc = 0.f;

    const int brow = t >> 2, bq = t & 3;
    const float* bsrc = fmap_tp1 + (size_t)brow * FSTRIDE + (size_t)l * CDIM + bq * 32;
    float4 pf[8];
    {
        const float4* p = reinterpret_cast<const float4*>(bsrc);
#pragma unroll
        for (int j = 0; j < 8; ++j) pf[j] = p[j];
    }

#pragma unroll 1
    for (int ch = 0; ch < 8; ++ch) {
        const int buf = ch & 1;
        const int bOff = buf ? OFF_B1 : OFF_B0;
        // quantize + stage B[buf] with per-token scale
        {
            float m = 0.f;
#pragma unroll
            for (int j = 0; j < 8; ++j) {
                m = fmaxf(m, fmaxf(fmaxf(fabsf(pf[j].x), fabsf(pf[j].y)),
                                   fmaxf(fabsf(pf[j].z), fabsf(pf[j].w))));
            }
            m = fmaxf(m, __shfl_xor_sync(0xffffffffu, m, 1));
            m = fmaxf(m, __shfl_xor_sync(0xffffffffu, m, 2));
            if (bq == 0) sB[buf * 64 + brow] = m * (1.0f / 127.0f);
            float inv = 127.0f / m;
            uint4 w0, w1;
            w0.x = pack4(pf[0], inv); w0.y = pack4(pf[1], inv);
            w0.z = pack4(pf[2], inv); w0.w = pack4(pf[3], inv);
            w1.x = pack4(pf[4], inv); w1.y = pack4(pf[5], inv);
            w1.z = pack4(pf[6], inv); w1.w = pack4(pf[7], inv);
            *reinterpret_cast<uint4*>(sm + bOff + brow * RS + bq * 32)      = w0;
            *reinterpret_cast<uint4*>(sm + bOff + brow * RS + bq * 32 + 16) = w1;
        }
        __syncthreads();
        if (ch < 7) {
            const float4* p = reinterpret_cast<const float4*>(
                bsrc + (size_t)(ch + 1) * 64 * FSTRIDE);
#pragma unroll
            for (int j = 0; j < 8; ++j) pf[j] = p[j];
        }
        float sb[4][2];
#pragma unroll
        for (int ni = 0; ni < 4; ++ni) {
            int nl = wx * 32 + ni * 8 + tig * 2;
            sb[ni][0] = sB[buf * 64 + nl];
            sb[ni][1] = sB[buf * 64 + nl + 1];
        }

        int c1[2][4][4], c2[2][4][4];
#pragma unroll
        for (int mi = 0; mi < 2; ++mi)
#pragma unroll
            for (int ni = 0; ni < 4; ++ni)
#pragma unroll
                for (int q = 0; q < 4; ++q) { c1[mi][ni][q] = 0; c2[mi][ni][q] = 0; }

#pragma unroll
        for (int ks = 0; ks < 4; ++ks) {
            uint32_t a1f[2][4], a2f[2][4], b[4][2];
#pragma unroll
            for (int mi = 0; mi < 2; ++mi) {
                uint32_t off = (wy * 32 + mi * 16 + aRowQ) * RS + ks * 32 + aKoffQ;
                LDSM4(a1f[mi][0], a1f[mi][1], a1f[mi][2], a1f[mi][3], sbase + OFF_A1 + off);
                LDSM4(a2f[mi][0], a2f[mi][1], a2f[mi][2], a2f[mi][3], sbase + OFF_A2 + off);
            }
#pragma unroll
            for (int nt = 0; nt < 2; ++nt) {
                uint32_t bd = sbase + bOff + (wx * 32 + nt * 16 + bRowQ) * RS
                            + ks * 32 + bKoffQ;
                LDSM4(b[nt * 2][0], b[nt * 2][1], b[nt * 2 + 1][0], b[nt * 2 + 1][1], bd);
            }
#pragma unroll
            for (int mi = 0; mi < 2; ++mi)
#pragma unroll
                for (int ni = 0; ni < 4; ++ni) {
                    mma32s8(c1[mi][ni], a1f[mi], b[ni]);
                    mma32s8(c2[mi][ni], a2f[mi], b[ni]);
                }
        }

        // dequant + fused sum-exp + diag
#pragma unroll
        for (int mi = 0; mi < 2; ++mi) {
            const int r0 = nb * 128 + wy * 32 + mi * 16 + g;
            const int r1 = r0 + 8;
#pragma unroll
            for (int ni = 0; ni < 4; ++ni) {
                const int col = ch * 64 + wx * 32 + ni * 8 + tig * 2;
                float u00 = __int2float_rn(c1[mi][ni][0]) * sa1v[mi * 2]     * sb[ni][0];
                float u01 = __int2float_rn(c1[mi][ni][1]) * sa1v[mi * 2]     * sb[ni][1];
                float u10 = __int2float_rn(c1[mi][ni][2]) * sa1v[mi * 2 + 1] * sb[ni][0];
                float u11 = __int2float_rn(c1[mi][ni][3]) * sa1v[mi * 2 + 1] * sb[ni][1];
                float v00 = __int2float_rn(c2[mi][ni][0]) * sa2v[mi * 2]     * sb[ni][0];
                float v01 = __int2float_rn(c2[mi][ni][1]) * sa2v[mi * 2]     * sb[ni][1];
                float v10 = __int2float_rn(c2[mi][ni][2]) * sa2v[mi * 2 + 1] * sb[ni][0];
                float v11 = __int2float_rn(c2[mi][ni][3]) * sa2v[mi * 2 + 1] * sb[ni][1];
                S1[mi * 2 + 0] += __expf(u00) + __expf(u01);
                S1[mi * 2 + 1] += __expf(u10) + __expf(u11);
                S2[mi * 2 + 0] += __expf(v00) + __expf(v01);
                S2[mi * 2 + 1] += __expf(v10) + __expf(v11);
                if (col     == r0) diagAcc += u00 + v00;
                if (col + 1 == r0) diagAcc += u01 + v01;
                if (col     == r1) diagAcc += u10 + v10;
                if (col + 1 == r1) diagAcc += u11 + v11;
            }
        }
    }

    // ---------------- Phase 3: reductions ----------------
#pragma unroll
    for (int slot = 0; slot < 4; ++slot) {
        float s1 = S1[slot], s2 = S2[slot];
        s1 += __shfl_xor_sync(0xffffffffu, s1, 1);
        s1 += __shfl_xor_sync(0xffffffffu, s1, 2);
        s2 += __shfl_xor_sync(0xffffffffu, s2, 1);
        s2 += __shfl_xor_sync(0xffffffffu, s2, 2);
        if (tig == 0) {
            int row = wy * 32 + (slot >> 1) * 16 + g + (slot & 1) * 8;
            atomicAdd(&rowS[row], s1);
            atomicAdd(&rowS[128 + row], s2);
        }
    }
    __syncthreads();

    float contrib = -diagAcc + __logf(rowS[t]);
#pragma unroll
    for (int off = 16; off > 0; off >>= 1)
        contrib += __shfl_down_sync(0xffffffffu, contrib, off);
    if (lane == 0) wred[warp] = contrib;
    __syncthreads();
    if (t == 0) {
        float v = 0.f;
#pragma unroll
        for (int w = 0; w < 8; ++w) v += wred[w];
        atomicAdd(&g_acc, (double)v);
    }
}

extern "C" void kernel_launch(void* const* d_in, const int* in_sizes, int n_in,
                              void* d_out, int out_size) {
    const float* f_t      = (const float*)d_in[0];
    const float* fmap_t   = (const float*)d_in[1];
    const float* fmap_tp1 = (const float*)d_in[2];
    const float* W1       = (const float*)d_in[3];
    const float* b1       = (const float*)d_in[4];
    const float* W2       = (const float*)d_in[5];
    const float* b2       = (const float*)d_in[6];
    float* out = (float*)d_out;

    cudaFuncSetAttribute(main_k, cudaFuncAttributeMaxDynamicSharedMemorySize, SMEM_TOTAL);

    preds1_k<<<NTOK, CDIM>>>(f_t, W1, b1);
    dim3 grid(NTOK / 128, LLOC);   // (4, 144)
    main_k<<<grid, 256, SMEM_TOTAL>>>(fmap_t, fmap_tp1, W2, b2);
    final_k<<<1, 1>>>(out);
}

// round 9
// speedup vs baseline: 2.2471x; 2.2471x over previous
#include <cuda_runtime.h>
#include <cuda_fp16.h>
#include <cstdint>

#define NTOK 512
#define CDIM 128
#define LLOC 144
#define DDIM 256
#define FSTRIDE (LLOC * CDIM)
#define SKB 272                   // main_k smem row stride (bytes, 136 halves)
#define PKB 528                   // preds1_k smem row stride (bytes, 264 halves)

// main_k smem byte offsets
#define OFF_A1   0
#define OFF_A2   34816            // 128*272
#define OFF_B    69632
#define OFF_ROWS 87040            // 256 floats
#define OFF_WRED 88064            // 8 floats
#define SMEM_TOTAL 88096
// preds1_k smem
#define P_OFF_B  67584            // 128*528
#define P_SMEM   135168

__device__ float  g_preds1[NTOK * CDIM];
__device__ double g_acc;

__device__ __forceinline__ uint32_t ph2(float x, float y) {
    __half2 h = __floats2half2_rn(x, y);
    return *reinterpret_cast<uint32_t*>(&h);
}
__device__ __forceinline__ float2 up2(uint32_t v) {
    return __half22float2(*reinterpret_cast<__half2*>(&v));
}
__device__ __forceinline__ void stage8h(char* tile, int row, int k0,
                                        const float* __restrict__ src) {
    float4 a = *reinterpret_cast<const float4*>(src);
    float4 b = *reinterpret_cast<const float4*>(src + 4);
    uint4 v;
    v.x = ph2(a.x, a.y); v.y = ph2(a.z, a.w);
    v.z = ph2(b.x, b.y); v.w = ph2(b.z, b.w);
    *reinterpret_cast<uint4*>(tile + row * SKB + k0 * 2) = v;
}

#define LDSM4(r0, r1, r2, r3, addr) \
    asm volatile("ldmatrix.sync.aligned.m8n8.x4.shared.b16 {%0,%1,%2,%3}, [%4];" \
                 : "=r"(r0), "=r"(r1), "=r"(r2), "=r"(r3) : "r"(addr))

__device__ __forceinline__ void mma16h(uint32_t* c, const uint32_t* a, const uint32_t* b) {
    asm volatile(
        "mma.sync.aligned.m16n8k16.row.col.f16.f16.f16.f16 "
        "{%0,%1}, {%2,%3,%4,%5}, {%6,%7}, {%0,%1};\n"
        : "+r"(c[0]), "+r"(c[1])
        : "r"(a[0]), "r"(a[1]), "r"(a[2]), "r"(a[3]), "r"(b[0]), "r"(b[1]));
}
__device__ __forceinline__ void mma16f(float* c, const uint32_t* a, const uint32_t* b) {
    asm volatile(
        "mma.sync.aligned.m16n8k16.row.col.f32.f16.f16.f32 "
        "{%0,%1,%2,%3}, {%4,%5,%6,%7}, {%8,%9}, {%0,%1,%2,%3};\n"
        : "+f"(c[0]), "+f"(c[1]), "+f"(c[2]), "+f"(c[3])
        : "r"(a[0]), "r"(a[1]), "r"(a[2]), "r"(a[3]), "r"(b[0]), "r"(b[1]));
}

// ---- preds1 = f_t @ W1^T + b1 as a single 512x128x256 tensor GEMM, 4 CTAs ----
__global__ void __launch_bounds__(256, 1)
preds1_k(const float* __restrict__ f_t,
         const float* __restrict__ W1,
         const float* __restrict__ b1) {
    extern __shared__ char psm[];
    const uint32_t sb = (uint32_t)__cvta_generic_to_shared(psm);
    const int t = threadIdx.x, lane = t & 31, warp = t >> 5;
    const int wy = warp >> 1, wx = warp & 1;       // 4 (M) x 2 (N); warp tile 32x64
    const int g = lane >> 2, tig = lane & 3;
    if (blockIdx.x == 0 && t == 0) g_acc = 0.0;

    {   // stage A (f_t slab) and B (full W1) as fp16: 128 floats per (row, half)
        int row = t >> 1, half = t & 1;
        const float4* sa = reinterpret_cast<const float4*>(
            f_t + (size_t)(blockIdx.x * 128 + row) * DDIM + half * 128);
        uint2* da = reinterpret_cast<uint2*>(psm + row * PKB + half * 256);
        const float4* sw = reinterpret_cast<const float4*>(
            W1 + (size_t)row * DDIM + half * 128);
        uint2* dw = reinterpret_cast<uint2*>(psm + P_OFF_B + row * PKB + half * 256);
#pragma unroll
        for (int j = 0; j < 32; ++j) {
            float4 a = sa[j];
            da[j] = make_uint2(ph2(a.x, a.y), ph2(a.z, a.w));
            float4 w = sw[j];
            dw[j] = make_uint2(ph2(w.x, w.y), ph2(w.z, w.w));
        }
    }
    __syncthreads();

    const uint32_t aRow = lane & 15, aKoff = ((lane >> 4) << 3);
    const uint32_t bRow = ((lane >> 4) << 3) + (lane & 7), bKoff = (((lane >> 3) & 1) << 3);

    float pc[2][8][4];
#pragma unroll
    for (int mi = 0; mi < 2; ++mi)
#pragma unroll
        for (int ni = 0; ni < 8; ++ni)
#pragma unroll
            for (int q = 0; q < 4; ++q) pc[mi][ni][q] = 0.f;

#pragma unroll
    for (int ks = 0; ks < 16; ++ks) {
        const int k0 = ks * 16;
        uint32_t a[2][4], b[8][2];
#pragma unroll
        for (int mi = 0; mi < 2; ++mi) {
            uint32_t ad = sb + (wy * 32 + mi * 16 + aRow) * PKB + (k0 + aKoff) * 2;
            LDSM4(a[mi][0], a[mi][1], a[mi][2], a[mi][3], ad);
        }
#pragma unroll
        for (int nt = 0; nt < 4; ++nt) {
            uint32_t bd = sb + P_OFF_B + (wx * 64 + nt * 16 + bRow) * PKB + (k0 + bKoff) * 2;
            LDSM4(b[nt * 2][0], b[nt * 2][1], b[nt * 2 + 1][0], b[nt * 2 + 1][1], bd);
        }
#pragma unroll
        for (int mi = 0; mi < 2; ++mi)
#pragma unroll
            for (int ni = 0; ni < 8; ++ni) mma16f(pc[mi][ni], a[mi], b[ni]);
    }

#pragma unroll
    for (int mi = 0; mi < 2; ++mi)
#pragma unroll
        for (int ni = 0; ni < 8; ++ni) {
            int row = blockIdx.x * 128 + wy * 32 + mi * 16 + g;
            int col = wx * 64 + ni * 8 + tig * 2;
            float bv0 = __ldg(b1 + col), bv1 = __ldg(b1 + col + 1);
            g_preds1[(size_t)row * CDIM + col]           = pc[mi][ni][0] + bv0;
            g_preds1[(size_t)row * CDIM + col + 1]       = pc[mi][ni][1] + bv1;
            g_preds1[(size_t)(row + 8) * CDIM + col]     = pc[mi][ni][2] + bv0;
            g_preds1[(size_t)(row + 8) * CDIM + col + 1] = pc[mi][ni][3] + bv1;
        }
}

__global__ void final_k(float* __restrict__ out) {
    out[0] = (float)(g_acc / (double)(LLOC * NTOK));
}

__global__ void __launch_bounds__(256, 1)
main_k(const float* __restrict__ fmap_t,
       const float* __restrict__ fmap_tp1,
       const float* __restrict__ W2,
       const float* __restrict__ b2) {
    extern __shared__ char sm[];
    const uint32_t sbase = (uint32_t)__cvta_generic_to_shared(sm);
    const uint32_t sbA1 = sbase + OFF_A1, sbA2 = sbase + OFF_A2, sbB = sbase + OFF_B;
    float* rowS = reinterpret_cast<float*>(sm + OFF_ROWS);
    float* wred = reinterpret_cast<float*>(sm + OFF_WRED);

    const int l    = blockIdx.y;
    const int nb   = blockIdx.x;
    const int t    = threadIdx.x;
    const int lane = t & 31, warp = t >> 5;
    const int wy   = warp >> 1, wx = warp & 1;
    const int g    = lane >> 2, tig = lane & 3;

    const uint32_t aRow  = lane & 15;
    const uint32_t aKoff = ((lane >> 4) << 3);
    const uint32_t bRow  = ((lane >> 4) << 3) + (lane & 7);
    const uint32_t bKoff = (((lane >> 3) & 1) << 3);

    // ---------------- Phase 0: stage A1 (preds1) and A2 (loc) as fp16 ----------------
#pragma unroll
    for (int j = 0; j < 8; ++j) {
        int idx = j * 256 + t, row = idx >> 4, k0 = (idx & 15) * 8;
        stage8h(sm + OFF_A1, row, k0, g_preds1 + (size_t)(nb * 128 + row) * CDIM + k0);
        stage8h(sm + OFF_A2, row, k0,
                fmap_t + (size_t)(nb * 128 + row) * FSTRIDE + l * CDIM + k0);
    }
    rowS[t] = 0.f;
    __syncthreads();

    // ---------------- Phase 1: preds2 = loc @ W2^T + b2 (fp16 acc) ----------------
    uint32_t pc[2][2][4][2];
#pragma unroll
    for (int p = 0; p < 2; ++p)
#pragma unroll
        for (int mi = 0; mi < 2; ++mi)
#pragma unroll
            for (int ni = 0; ni < 4; ++ni) { pc[p][mi][ni][0] = 0u; pc[p][mi][ni][1] = 0u; }

#pragma unroll 1
    for (int p = 0; p < 2; ++p) {
        if (p) __syncthreads();
        {   // W2 rows [p*64, p*64+64) -> B tile
            int row = t >> 2, k0 = (t & 3) * 32;
            const float* src = W2 + (size_t)(p * 64 + row) * CDIM + k0;
#pragma unroll
            for (int j = 0; j < 4; ++j) stage8h(sm + OFF_B, row, k0 + j * 8, src + j * 8);
        }
        __syncthreads();

#pragma unroll
        for (int ks = 0; ks < 8; ++ks) {
            const int k0 = ks * 16;
            uint32_t a[2][4], b[4][2];
#pragma unroll
            for (int mi = 0; mi < 2; ++mi) {
                uint32_t ad = sbA2 + (wy * 32 + mi * 16 + aRow) * SKB + (k0 + aKoff) * 2;
                LDSM4(a[mi][0], a[mi][1], a[mi][2], a[mi][3], ad);
            }
#pragma unroll
            for (int nt = 0; nt < 2; ++nt) {
                uint32_t bd = sbB + (wx * 32 + nt * 16 + bRow) * SKB + (k0 + bKoff) * 2;
                LDSM4(b[nt * 2][0], b[nt * 2][1], b[nt * 2 + 1][0], b[nt * 2 + 1][1], bd);
            }
#pragma unroll
            for (int mi = 0; mi < 2; ++mi)
#pragma unroll
                for (int ni = 0; ni < 4; ++ni) mma16h(pc[p][mi][ni], a[mi], b[ni]);
        }
    }
    __syncthreads();                      // all reads of A2 (loc) complete

    // overwrite A2 with preds2 (+b2) as fp16
#pragma unroll
    for (int p = 0; p < 2; ++p)
#pragma unroll
        for (int mi = 0; mi < 2; ++mi)
#pragma unroll
            for (int ni = 0; ni < 4; ++ni) {
                int row = wy * 32 + mi * 16 + g;
                int col = p * 64 + wx * 32 + ni * 8 + tig * 2;
                float bv0 = __ldg(b2 + col), bv1 = __ldg(b2 + col + 1);
                float2 lo = up2(pc[p][mi][ni][0]), hi = up2(pc[p][mi][ni][1]);
                *reinterpret_cast<uint32_t*>(sm + OFF_A2 + row * SKB + col * 2) =
                    ph2(lo.x + bv0, lo.y + bv1);
                *reinterpret_cast<uint32_t*>(sm + OFF_A2 + (row + 8) * SKB + col * 2) =
                    ph2(hi.x + bv0, hi.y + bv1);
            }

    // ---------------- Phase 2: main loop over 8 pos chunks of 64 ----------------
    float S1[4] = {0.f, 0.f, 0.f, 0.f};
    float S2[4] = {0.f, 0.f, 0.f, 0.f};
    float diagAcc = 0.f;

    const int brow = t >> 2, bq = t & 3;
    const float* bsrc = fmap_tp1 + (size_t)brow * FSTRIDE + (size_t)l * CDIM + bq * 32;
    float4 pf[8];
    {
        const float4* p = reinterpret_cast<const float4*>(bsrc);
#pragma unroll
        for (int j = 0; j < 8; ++j) pf[j] = p[j];
    }

#pragma unroll 1
    for (int ch = 0; ch < 8; ++ch) {
        __syncthreads();                  // B tile free
        {
            char* dst = sm + OFF_B;
#pragma unroll
            for (int j = 0; j < 4; ++j) {
                float4 u = pf[2 * j], v = pf[2 * j + 1];
                uint4 w;
                w.x = ph2(u.x, u.y); w.y = ph2(u.z, u.w);
                w.z = ph2(v.x, v.y); w.w = ph2(v.z, v.w);
                *reinterpret_cast<uint4*>(dst + brow * SKB + (bq * 32 + j * 8) * 2) = w;
            }
        }
        __syncthreads();
        if (ch < 7) {
            const float4* p = reinterpret_cast<const float4*>(
                bsrc + (size_t)(ch + 1) * 64 * FSTRIDE);
#pragma unroll
            for (int j = 0; j < 8; ++j) pf[j] = p[j];
        }

        uint32_t c1[2][4][2], c2[2][4][2];
#pragma unroll
        for (int mi = 0; mi < 2; ++mi)
#pragma unroll
            for (int ni = 0; ni < 4; ++ni) {
                c1[mi][ni][0] = 0u; c1[mi][ni][1] = 0u;
                c2[mi][ni][0] = 0u; c2[mi][ni][1] = 0u;
            }

#pragma unroll
        for (int ks = 0; ks < 8; ++ks) {
            const int k0 = ks * 16;
            uint32_t a1f[2][4], a2f[2][4], b[4][2];
#pragma unroll
            for (int mi = 0; mi < 2; ++mi) {
                uint32_t off = (wy * 32 + mi * 16 + aRow) * SKB + (k0 + aKoff) * 2;
                LDSM4(a1f[mi][0], a1f[mi][1], a1f[mi][2], a1f[mi][3], sbA1 + off);
                LDSM4(a2f[mi][0], a2f[mi][1], a2f[mi][2], a2f[mi][3], sbA2 + off);
            }
#pragma unroll
            for (int nt = 0; nt < 2; ++nt) {
                uint32_t bd = sbB + (wx * 32 + nt * 16 + bRow) * SKB + (k0 + bKoff) * 2;
                LDSM4(b[nt * 2][0], b[nt * 2][1], b[nt * 2 + 1][0], b[nt * 2 + 1][1], bd);
            }
#pragma unroll
            for (int mi = 0; mi < 2; ++mi)
#pragma unroll
                for (int ni = 0; ni < 4; ++ni) {
                    mma16h(c1[mi][ni], a1f[mi], b[ni]);
                    mma16h(c2[mi][ni], a2f[mi], b[ni]);
                }
        }

        // fused epilogue: sum-exp + diag (|logit| < ~60 << 65504, no overflow)
#pragma unroll
        for (int mi = 0; mi < 2; ++mi) {
            const int r0 = nb * 128 + wy * 32 + mi * 16 + g;
            const int r1 = r0 + 8;
#pragma unroll
            for (int ni = 0; ni < 4; ++ni) {
                const int col = ch * 64 + wx * 32 + ni * 8 + tig * 2;
                float2 v1lo = up2(c1[mi][ni][0]), v1hi = up2(c1[mi][ni][1]);
                float2 v2lo = up2(c2[mi][ni][0]), v2hi = up2(c2[mi][ni][1]);
                S1[mi * 2 + 0] += __expf(v1lo.x) + __expf(v1lo.y);
                S1[mi * 2 + 1] += __expf(v1hi.x) + __expf(v1hi.y);
                S2[mi * 2 + 0] += __expf(v2lo.x) + __expf(v2lo.y);
                S2[mi * 2 + 1] += __expf(v2hi.x) + __expf(v2hi.y);
                if (col     == r0) diagAcc += v1lo.x + v2lo.x;
                if (col + 1 == r0) diagAcc += v1lo.y + v2lo.y;
                if (col     == r1) diagAcc += v1hi.x + v2hi.x;
                if (col + 1 == r1) diagAcc += v1hi.y + v2hi.y;
            }
        }
    }

    // ---------------- Phase 3: reductions ----------------
#pragma unroll
    for (int slot = 0; slot < 4; ++slot) {
        float s1 = S1[slot], s2 = S2[slot];
        s1 += __shfl_xor_sync(0xffffffffu, s1, 1);
        s1 += __shfl_xor_sync(0xffffffffu, s1, 2);
        s2 += __shfl_xor_sync(0xffffffffu, s2, 1);
        s2 += __shfl_xor_sync(0xffffffffu, s2, 2);
        if (tig == 0) {
            int row = wy * 32 + (slot >> 1) * 16 + g + (slot & 1) * 8;
            atomicAdd(&rowS[row], s1);
            atomicAdd(&rowS[128 + row], s2);
        }
    }
    __syncthreads();

    float contrib = -diagAcc + __logf(rowS[t]);
#pragma unroll
    for (int off = 16; off > 0; off >>= 1)
        contrib += __shfl_down_sync(0xffffffffu, contrib, off);
    if (lane == 0) wred[warp] = contrib;
    __syncthreads();
    if (t == 0) {
        float v = 0.f;
#pragma unroll
        for (int w = 0; w < 8; ++w) v += wred[w];
        atomicAdd(&g_acc, (double)v);
    }
}

extern "C" void kernel_launch(void* const* d_in, const int* in_sizes, int n_in,
                              void* d_out, int out_size) {
    const float* f_t      = (const float*)d_in[0];
    const float* fmap_t   = (const float*)d_in[1];
    const float* fmap_tp1 = (const float*)d_in[2];
    const float* W1       = (const float*)d_in[3];
    const float* b1       = (const float*)d_in[4];
    const float* W2       = (const float*)d_in[5];
    const float* b2       = (const float*)d_in[6];
    float* out = (float*)d_out;

    cudaFuncSetAttribute(preds1_k, cudaFuncAttributeMaxDynamicSharedMemorySize, P_SMEM);
    cudaFuncSetAttribute(main_k, cudaFuncAttributeMaxDynamicSharedMemorySize, SMEM_TOTAL);

    preds1_k<<<NTOK / 128, 256, P_SMEM>>>(f_t, W1, b1);
    dim3 grid(NTOK / 128, LLOC);   // (4, 144)
    main_k<<<grid, 256, SMEM_TOTAL>>>(fmap_t, fmap_tp1, W2, b2);
    final_k<<<1, 1>>>(out);
}

// round 10
// speedup vs baseline: 2.3179x; 1.0315x over previous
#include <cuda_runtime.h>
#include <cuda_fp16.h>
#include <cstdint>

#define NTOK 512
#define CDIM 128
#define LLOC 144
#define DDIM 256
#define FSTRIDE (LLOC * CDIM)
#define SKB 272                   // main_k smem row stride (bytes, 136 halves)
#define PKB 528                   // preds1_k smem row stride (bytes, 264 halves)

// main_k smem byte offsets
#define OFF_A1   0
#define OFF_A2   34816            // 128*272
#define OFF_B    69632
#define OFF_ROWS 87040            // 256 floats
#define OFF_WRED 88064            // 8 floats
#define SMEM_PAD_TOTAL 118784     // forces 1 CTA/SM (>114KB)
// preds1_k smem
#define P_OFF_B  67584            // 128*528
#define P_SMEM   101376           // + 64*528

__device__ float  g_preds1[NTOK * CDIM];
__device__ double g_acc;

__device__ __forceinline__ uint32_t ph2(float x, float y) {
    __half2 h = __floats2half2_rn(x, y);
    return *reinterpret_cast<uint32_t*>(&h);
}
__device__ __forceinline__ float2 up2(uint32_t v) {
    return __half22float2(*reinterpret_cast<__half2*>(&v));
}
__device__ __forceinline__ void stage8h(char* tile, int row, int k0,
                                        const float* __restrict__ src) {
    float4 a = *reinterpret_cast<const float4*>(src);
    float4 b = *reinterpret_cast<const float4*>(src + 4);
    uint4 v;
    v.x = ph2(a.x, a.y); v.y = ph2(a.z, a.w);
    v.z = ph2(b.x, b.y); v.w = ph2(b.z, b.w);
    *reinterpret_cast<uint4*>(tile + row * SKB + k0 * 2) = v;
}

#define LDSM4(r0, r1, r2, r3, addr) \
    asm volatile("ldmatrix.sync.aligned.m8n8.x4.shared.b16 {%0,%1,%2,%3}, [%4];" \
                 : "=r"(r0), "=r"(r1), "=r"(r2), "=r"(r3) : "r"(addr))

__device__ __forceinline__ void mma16h(uint32_t* c, const uint32_t* a, const uint32_t* b) {
    asm volatile(
        "mma.sync.aligned.m16n8k16.row.col.f16.f16.f16.f16 "
        "{%0,%1}, {%2,%3,%4,%5}, {%6,%7}, {%0,%1};\n"
        : "+r"(c[0]), "+r"(c[1])
        : "r"(a[0]), "r"(a[1]), "r"(a[2]), "r"(a[3]), "r"(b[0]), "r"(b[1]));
}
__device__ __forceinline__ void mma16f(float* c, const uint32_t* a, const uint32_t* b) {
    asm volatile(
        "mma.sync.aligned.m16n8k16.row.col.f32.f16.f16.f32 "
        "{%0,%1,%2,%3}, {%4,%5,%6,%7}, {%8,%9}, {%0,%1,%2,%3};\n"
        : "+f"(c[0]), "+f"(c[1]), "+f"(c[2]), "+f"(c[3])
        : "r"(a[0]), "r"(a[1]), "r"(a[2]), "r"(a[3]), "r"(b[0]), "r"(b[1]));
}

// ---- preds1 = f_t @ W1^T + b1: grid (4,2), per CTA M=128 N=64 K=256 ----
__global__ void __launch_bounds__(256, 1)
preds1_k(const float* __restrict__ f_t,
         const float* __restrict__ W1,
         const float* __restrict__ b1) {
    extern __shared__ char psm[];
    const uint32_t sb = (uint32_t)__cvta_generic_to_shared(psm);
    const int nb = blockIdx.x, nh = blockIdx.y;
    const int t = threadIdx.x, lane = t & 31, warp = t >> 5;
    const int wy = warp >> 1, wx = warp & 1;       // 4 (M) x 2 (N); warp tile 32x32
    const int g = lane >> 2, tig = lane & 3;
    if (nb == 0 && nh == 0 && t == 0) g_acc = 0.0;

    {   // stage A rows (f_t slab): thread -> (row = t>>1, half128 = t&1)
        int row = t >> 1, half = t & 1;
        const float4* sa = reinterpret_cast<const float4*>(
            f_t + (size_t)(nb * 128 + row) * DDIM + half * 128);
        uint2* da = reinterpret_cast<uint2*>(psm + row * PKB + half * 256);
#pragma unroll
        for (int j = 0; j < 32; ++j) {
            float4 a = sa[j];
            da[j] = make_uint2(ph2(a.x, a.y), ph2(a.z, a.w));
        }
    }
    {   // stage B rows (W1 slice, 64 rows): thread -> (row = t>>2, quarter = t&3)
        int row = t >> 2, q = t & 3;
        const float4* sw = reinterpret_cast<const float4*>(
            W1 + (size_t)(nh * 64 + row) * DDIM + q * 64);
        uint2* dw = reinterpret_cast<uint2*>(psm + P_OFF_B + row * PKB + q * 128);
#pragma unroll
        for (int j = 0; j < 16; ++j) {
            float4 w = sw[j];
            dw[j] = make_uint2(ph2(w.x, w.y), ph2(w.z, w.w));
        }
    }
    __syncthreads();

    const uint32_t aRow = lane & 15, aKoff = ((lane >> 4) << 3);
    const uint32_t bRow = ((lane >> 4) << 3) + (lane & 7), bKoff = (((lane >> 3) & 1) << 3);

    float pc[2][4][4];
#pragma unroll
    for (int mi = 0; mi < 2; ++mi)
#pragma unroll
        for (int ni = 0; ni < 4; ++ni)
#pragma unroll
            for (int q = 0; q < 4; ++q) pc[mi][ni][q] = 0.f;

#pragma unroll 4
    for (int ks = 0; ks < 16; ++ks) {
        const int k0 = ks * 16;
        uint32_t a[2][4], b[4][2];
#pragma unroll
        for (int mi = 0; mi < 2; ++mi) {
            uint32_t ad = sb + (wy * 32 + mi * 16 + aRow) * PKB + (k0 + aKoff) * 2;
            LDSM4(a[mi][0], a[mi][1], a[mi][2], a[mi][3], ad);
        }
#pragma unroll
        for (int nt = 0; nt < 2; ++nt) {
            uint32_t bd = sb + P_OFF_B + (wx * 32 + nt * 16 + bRow) * PKB + (k0 + bKoff) * 2;
            LDSM4(b[nt * 2][0], b[nt * 2][1], b[nt * 2 + 1][0], b[nt * 2 + 1][1], bd);
        }
#pragma unroll
        for (int mi = 0; mi < 2; ++mi)
#pragma unroll
            for (int ni = 0; ni < 4; ++ni) mma16f(pc[mi][ni], a[mi], b[ni]);
    }

#pragma unroll
    for (int mi = 0; mi < 2; ++mi)
#pragma unroll
        for (int ni = 0; ni < 4; ++ni) {
            int row = nb * 128 + wy * 32 + mi * 16 + g;
            int col = nh * 64 + wx * 32 + ni * 8 + tig * 2;
            float bv0 = __ldg(b1 + col), bv1 = __ldg(b1 + col + 1);
            g_preds1[(size_t)row * CDIM + col]           = pc[mi][ni][0] + bv0;
            g_preds1[(size_t)row * CDIM + col + 1]       = pc[mi][ni][1] + bv1;
            g_preds1[(size_t)(row + 8) * CDIM + col]     = pc[mi][ni][2] + bv0;
            g_preds1[(size_t)(row + 8) * CDIM + col + 1] = pc[mi][ni][3] + bv1;
        }
}

__global__ void final_k(float* __restrict__ out) {
    out[0] = (float)(g_acc / (double)(LLOC * NTOK));
}

__global__ void __launch_bounds__(256, 1)
main_k(const float* __restrict__ fmap_t,
       const float* __restrict__ fmap_tp1,
       const float* __restrict__ W2,
       const float* __restrict__ b2) {
    extern __shared__ char sm[];
    const uint32_t sbase = (uint32_t)__cvta_generic_to_shared(sm);
    const uint32_t sbA1 = sbase + OFF_A1, sbA2 = sbase + OFF_A2, sbB = sbase + OFF_B;
    float* rowS = reinterpret_cast<float*>(sm + OFF_ROWS);
    float* wred = reinterpret_cast<float*>(sm + OFF_WRED);

    const int l    = blockIdx.y;
    const int nb   = blockIdx.x;
    const int t    = threadIdx.x;
    const int lane = t & 31, warp = t >> 5;
    const int wy   = warp >> 1, wx = warp & 1;
    const int g    = lane >> 2, tig = lane & 3;

    const uint32_t aRow  = lane & 15;
    const uint32_t aKoff = ((lane >> 4) << 3);
    const uint32_t bRow  = ((lane >> 4) << 3) + (lane & 7);
    const uint32_t bKoff = (((lane >> 3) & 1) << 3);

    // ---------------- Phase 0: stage A1 (preds1) and A2 (loc) as fp16 ----------------
#pragma unroll
    for (int j = 0; j < 8; ++j) {
        int idx = j * 256 + t, row = idx >> 4, k0 = (idx & 15) * 8;
        stage8h(sm + OFF_A1, row, k0, g_preds1 + (size_t)(nb * 128 + row) * CDIM + k0);
        stage8h(sm + OFF_A2, row, k0,
                fmap_t + (size_t)(nb * 128 + row) * FSTRIDE + l * CDIM + k0);
    }
    rowS[t] = 0.f;
    __syncthreads();

    // ---------------- Phase 1: preds2 = loc @ W2^T + b2 (fp16 acc) ----------------
    uint32_t pc[2][2][4][2];
#pragma unroll
    for (int p = 0; p < 2; ++p)
#pragma unroll
        for (int mi = 0; mi < 2; ++mi)
#pragma unroll
            for (int ni = 0; ni < 4; ++ni) { pc[p][mi][ni][0] = 0u; pc[p][mi][ni][1] = 0u; }

#pragma unroll 1
    for (int p = 0; p < 2; ++p) {
        if (p) __syncthreads();
        {   // W2 rows [p*64, p*64+64) -> B tile
            int row = t >> 2, k0 = (t & 3) * 32;
            const float* src = W2 + (size_t)(p * 64 + row) * CDIM + k0;
#pragma unroll
            for (int j = 0; j < 4; ++j) stage8h(sm + OFF_B, row, k0 + j * 8, src + j * 8);
        }
        __syncthreads();

#pragma unroll
        for (int ks = 0; ks < 8; ++ks) {
            const int k0 = ks * 16;
            uint32_t a[2][4], b[4][2];
#pragma unroll
            for (int mi = 0; mi < 2; ++mi) {
                uint32_t ad = sbA2 + (wy * 32 + mi * 16 + aRow) * SKB + (k0 + aKoff) * 2;
                LDSM4(a[mi][0], a[mi][1], a[mi][2], a[mi][3], ad);
            }
#pragma unroll
            for (int nt = 0; nt < 2; ++nt) {
                uint32_t bd = sbB + (wx * 32 + nt * 16 + bRow) * SKB + (k0 + bKoff) * 2;
                LDSM4(b[nt * 2][0], b[nt * 2][1], b[nt * 2 + 1][0], b[nt * 2 + 1][1], bd);
            }
#pragma unroll
            for (int mi = 0; mi < 2; ++mi)
#pragma unroll
                for (int ni = 0; ni < 4; ++ni) mma16h(pc[p][mi][ni], a[mi], b[ni]);
        }
    }
    __syncthreads();                      // all reads of A2 (loc) complete

    // overwrite A2 with preds2 (+b2) as fp16
#pragma unroll
    for (int p = 0; p < 2; ++p)
#pragma unroll
        for (int mi = 0; mi < 2; ++mi)
#pragma unroll
            for (int ni = 0; ni < 4; ++ni) {
                int row = wy * 32 + mi * 16 + g;
                int col = p * 64 + wx * 32 + ni * 8 + tig * 2;
                float bv0 = __ldg(b2 + col), bv1 = __ldg(b2 + col + 1);
                float2 lo = up2(pc[p][mi][ni][0]), hi = up2(pc[p][mi][ni][1]);
                *reinterpret_cast<uint32_t*>(sm + OFF_A2 + row * SKB + col * 2) =
                    ph2(lo.x + bv0, lo.y + bv1);
                *reinterpret_cast<uint32_t*>(sm + OFF_A2 + (row + 8) * SKB + col * 2) =
                    ph2(hi.x + bv0, hi.y + bv1);
            }

    // ---------------- Phase 2: main loop over 8 pos chunks of 64 ----------------
    float S1[4] = {0.f, 0.f, 0.f, 0.f};
    float S2[4] = {0.f, 0.f, 0.f, 0.f};
    float diagAcc = 0.f;

    const int brow = t >> 2, bq = t & 3;
    const float* bsrc = fmap_tp1 + (size_t)brow * FSTRIDE + (size_t)l * CDIM + bq * 32;
    float4 pf[8];
    {
        const float4* p = reinterpret_cast<const float4*>(bsrc);
#pragma unroll
        for (int j = 0; j < 8; ++j) pf[j] = p[j];
    }

#pragma unroll 1
    for (int ch = 0; ch < 8; ++ch) {
        __syncthreads();                  // B tile free
        {
            char* dst = sm + OFF_B;
#pragma unroll
            for (int j = 0; j < 4; ++j) {
                float4 u = pf[2 * j], v = pf[2 * j + 1];
                uint4 w;
                w.x = ph2(u.x, u.y); w.y = ph2(u.z, u.w);
                w.z = ph2(v.x, v.y); w.w = ph2(v.z, v.w);
                *reinterpret_cast<uint4*>(dst + brow * SKB + (bq * 32 + j * 8) * 2) = w;
            }
        }
        __syncthreads();
        if (ch < 7) {
            const float4* p = reinterpret_cast<const float4*>(
                bsrc + (size_t)(ch + 1) * 64 * FSTRIDE);
#pragma unroll
            for (int j = 0; j < 8; ++j) pf[j] = p[j];
        }

        uint32_t c1[2][4][2], c2[2][4][2];
#pragma unroll
        for (int mi = 0; mi < 2; ++mi)
#pragma unroll
            for (int ni = 0; ni < 4; ++ni) {
                c1[mi][ni][0] = 0u; c1[mi][ni][1] = 0u;
                c2[mi][ni][0] = 0u; c2[mi][ni][1] = 0u;
            }

#pragma unroll
        for (int ks = 0; ks < 8; ++ks) {
            const int k0 = ks * 16;
            uint32_t a1f[2][4], a2f[2][4], b[4][2];
#pragma unroll
            for (int mi = 0; mi < 2; ++mi) {
                uint32_t off = (wy * 32 + mi * 16 + aRow) * SKB + (k0 + aKoff) * 2;
                LDSM4(a1f[mi][0], a1f[mi][1], a1f[mi][2], a1f[mi][3], sbA1 + off);
                LDSM4(a2f[mi][0], a2f[mi][1], a2f[mi][2], a2f[mi][3], sbA2 + off);
            }
#pragma unroll
            for (int nt = 0; nt < 2; ++nt) {
                uint32_t bd = sbB + (wx * 32 + nt * 16 + bRow) * SKB + (k0 + bKoff) * 2;
                LDSM4(b[nt * 2][0], b[nt * 2][1], b[nt * 2 + 1][0], b[nt * 2 + 1][1], bd);
            }
#pragma unroll
            for (int mi = 0; mi < 2; ++mi)
#pragma unroll
                for (int ni = 0; ni < 4; ++ni) {
                    mma16h(c1[mi][ni], a1f[mi], b[ni]);
                    mma16h(c2[mi][ni], a2f[mi], b[ni]);
                }
        }

        // fused epilogue: sum-exp + diag (|logit| < ~60 << 65504, no overflow)
#pragma unroll
        for (int mi = 0; mi < 2; ++mi) {
            const int r0 = nb * 128 + wy * 32 + mi * 16 + g;
            const int r1 = r0 + 8;
#pragma unroll
            for (int ni = 0; ni < 4; ++ni) {
                const int col = ch * 64 + wx * 32 + ni * 8 + tig * 2;
                float2 v1lo = up2(c1[mi][ni][0]), v1hi = up2(c1[mi][ni][1]);
                float2 v2lo = up2(c2[mi][ni][0]), v2hi = up2(c2[mi][ni][1]);
                S1[mi * 2 + 0] += __expf(v1lo.x) + __expf(v1lo.y);
                S1[mi * 2 + 1] += __expf(v1hi.x) + __expf(v1hi.y);
                S2[mi * 2 + 0] += __expf(v2lo.x) + __expf(v2lo.y);
                S2[mi * 2 + 1] += __expf(v2hi.x) + __expf(v2hi.y);
                if (col     == r0) diagAcc += v1lo.x + v2lo.x;
                if (col + 1 == r0) diagAcc += v1lo.y + v2lo.y;
                if (col     == r1) diagAcc += v1hi.x + v2hi.x;
                if (col + 1 == r1) diagAcc += v1hi.y + v2hi.y;
            }
        }
    }

    // ---------------- Phase 3: reductions ----------------
#pragma unroll
    for (int slot = 0; slot < 4; ++slot) {
        float s1 = S1[slot], s2 = S2[slot];
        s1 += __shfl_xor_sync(0xffffffffu, s1, 1);
        s1 += __shfl_xor_sync(0xffffffffu, s1, 2);
        s2 += __shfl_xor_sync(0xffffffffu, s2, 1);
        s2 += __shfl_xor_sync(0xffffffffu, s2, 2);
        if (tig == 0) {
            int row = wy * 32 + (slot >> 1) * 16 + g + (slot & 1) * 8;
            atomicAdd(&rowS[row], s1);
            atomicAdd(&rowS[128 + row], s2);
        }
    }
    __syncthreads();

    float contrib = -diagAcc + __logf(rowS[t]);
#pragma unroll
    for (int off = 16; off > 0; off >>= 1)
        contrib += __shfl_down_sync(0xffffffffu, contrib, off);
    if (lane == 0) wred[warp] = contrib;
    __syncthreads();
    if (t == 0) {
        float v = 0.f;
#pragma unroll
        for (int w = 0; w < 8; ++w) v += wred[w];
        atomicAdd(&g_acc, (double)v);
    }
}

extern "C" void kernel_launch(void* const* d_in, const int* in_sizes, int n_in,
                              void* d_out, int out_size) {
    const float* f_t      = (const float*)d_in[0];
    const float* fmap_t   = (const float*)d_in[1];
    const float* fmap_tp1 = (const float*)d_in[2];
    const float* W1       = (const float*)d_in[3];
    const float* b1       = (const float*)d_in[4];
    const float* W2       = (const float*)d_in[5];
    const float* b2       = (const float*)d_in[6];
    float* out = (float*)d_out;

    cudaFuncSetAttribute(preds1_k, cudaFuncAttributeMaxDynamicSharedMemorySize, P_SMEM);
    cudaFuncSetAttribute(main_k, cudaFuncAttributeMaxDynamicSharedMemorySize, SMEM_PAD_TOTAL);

    dim3 pgrid(NTOK / 128, 2);     // (4, 2)
    preds1_k<<<pgrid, 256, P_SMEM>>>(f_t, W1, b1);
    dim3 grid(NTOK / 128, LLOC);   // (4, 144)
    main_k<<<grid, 256, SMEM_PAD_TOTAL>>>(fmap_t, fmap_tp1, W2, b2);
    final_k<<<1, 1>>>(out);
}

// round 11
// speedup vs baseline: 2.7214x; 1.1741x over previous
#include <cuda_runtime.h>
#include <cuda_fp16.h>
#include <cstdint>

#define NTOK 512
#define CDIM 128
#define LLOC 144
#define DDIM 256
#define FSTRIDE (LLOC * CDIM)
#define SKB 272                   // main_k smem row stride (bytes, 136 halves)
#define PKB 528                   // preds1_k smem row stride (bytes, 264 halves)

// main_k smem byte offsets
#define OFF_A1   0
#define OFF_A2   34816            // 128*272
#define OFF_B    69632
#define OFF_ROWS 87040            // 256 floats
#define OFF_WRED 88064            // 8 floats
#define SMEM_TOTAL 88096          // 2 CTAs/SM fit (176KB < 228KB)
// preds1_k smem
#define P_OFF_B  67584            // 128*528
#define P_SMEM   101376           // + 64*528

__device__ float  g_preds1[NTOK * CDIM];
__device__ double g_acc;

__device__ __forceinline__ uint32_t ph2(float x, float y) {
    __half2 h = __floats2half2_rn(x, y);
    return *reinterpret_cast<uint32_t*>(&h);
}
__device__ __forceinline__ float2 up2(uint32_t v) {
    return __half22float2(*reinterpret_cast<__half2*>(&v));
}
__device__ __forceinline__ void stage8h(char* tile, int row, int k0,
                                        const float* __restrict__ src) {
    float4 a = *reinterpret_cast<const float4*>(src);
    float4 b = *reinterpret_cast<const float4*>(src + 4);
    uint4 v;
    v.x = ph2(a.x, a.y); v.y = ph2(a.z, a.w);
    v.z = ph2(b.x, b.y); v.w = ph2(b.z, b.w);
    *reinterpret_cast<uint4*>(tile + row * SKB + k0 * 2) = v;
}

#define LDSM4(r0, r1, r2, r3, addr) \
    asm volatile("ldmatrix.sync.aligned.m8n8.x4.shared.b16 {%0,%1,%2,%3}, [%4];" \
                 : "=r"(r0), "=r"(r1), "=r"(r2), "=r"(r3) : "r"(addr))

__device__ __forceinline__ void mma16h(uint32_t* c, const uint32_t* a, const uint32_t* b) {
    asm volatile(
        "mma.sync.aligned.m16n8k16.row.col.f16.f16.f16.f16 "
        "{%0,%1}, {%2,%3,%4,%5}, {%6,%7}, {%0,%1};\n"
        : "+r"(c[0]), "+r"(c[1])
        : "r"(a[0]), "r"(a[1]), "r"(a[2]), "r"(a[3]), "r"(b[0]), "r"(b[1]));
}
__device__ __forceinline__ void mma16f(float* c, const uint32_t* a, const uint32_t* b) {
    asm volatile(
        "mma.sync.aligned.m16n8k16.row.col.f32.f16.f16.f32 "
        "{%0,%1,%2,%3}, {%4,%5,%6,%7}, {%8,%9}, {%0,%1,%2,%3};\n"
        : "+f"(c[0]), "+f"(c[1]), "+f"(c[2]), "+f"(c[3])
        : "r"(a[0]), "r"(a[1]), "r"(a[2]), "r"(a[3]), "r"(b[0]), "r"(b[1]));
}

// ---- preds1 = f_t @ W1^T + b1: grid (4,2), per CTA M=128 N=64 K=256 ----
__global__ void __launch_bounds__(256, 2)
preds1_k(const float* __restrict__ f_t,
         const float* __restrict__ W1,
         const float* __restrict__ b1) {
    extern __shared__ char psm[];
    const uint32_t sb = (uint32_t)__cvta_generic_to_shared(psm);
    const int nb = blockIdx.x, nh = blockIdx.y;
    const int t = threadIdx.x, lane = t & 31, warp = t >> 5;
    const int wy = warp >> 1, wx = warp & 1;       // 4 (M) x 2 (N); warp tile 32x32
    const int g = lane >> 2, tig = lane & 3;
    if (nb == 0 && nh == 0 && t == 0) g_acc = 0.0;

    {   // stage A rows (f_t slab): thread -> (row = t>>1, half128 = t&1)
        int row = t >> 1, half = t & 1;
        const float4* sa = reinterpret_cast<const float4*>(
            f_t + (size_t)(nb * 128 + row) * DDIM + half * 128);
        uint2* da = reinterpret_cast<uint2*>(psm + row * PKB + half * 256);
#pragma unroll
        for (int j = 0; j < 32; ++j) {
            float4 a = sa[j];
            da[j] = make_uint2(ph2(a.x, a.y), ph2(a.z, a.w));
        }
    }
    {   // stage B rows (W1 slice, 64 rows): thread -> (row = t>>2, quarter = t&3)
        int row = t >> 2, q = t & 3;
        const float4* sw = reinterpret_cast<const float4*>(
            W1 + (size_t)(nh * 64 + row) * DDIM + q * 64);
        uint2* dw = reinterpret_cast<uint2*>(psm + P_OFF_B + row * PKB + q * 128);
#pragma unroll
        for (int j = 0; j < 16; ++j) {
            float4 w = sw[j];
            dw[j] = make_uint2(ph2(w.x, w.y), ph2(w.z, w.w));
        }
    }
    __syncthreads();

    const uint32_t aRow = lane & 15, aKoff = ((lane >> 4) << 3);
    const uint32_t bRow = ((lane >> 4) << 3) + (lane & 7), bKoff = (((lane >> 3) & 1) << 3);

    float pc[2][4][4];
#pragma unroll
    for (int mi = 0; mi < 2; ++mi)
#pragma unroll
        for (int ni = 0; ni < 4; ++ni)
#pragma unroll
            for (int q = 0; q < 4; ++q) pc[mi][ni][q] = 0.f;

#pragma unroll 2
    for (int ks = 0; ks < 16; ++ks) {
        const int k0 = ks * 16;
        uint32_t a[2][4], b[4][2];
#pragma unroll
        for (int mi = 0; mi < 2; ++mi) {
            uint32_t ad = sb + (wy * 32 + mi * 16 + aRow) * PKB + (k0 + aKoff) * 2;
            LDSM4(a[mi][0], a[mi][1], a[mi][2], a[mi][3], ad);
        }
#pragma unroll
        for (int nt = 0; nt < 2; ++nt) {
            uint32_t bd = sb + P_OFF_B + (wx * 32 + nt * 16 + bRow) * PKB + (k0 + bKoff) * 2;
            LDSM4(b[nt * 2][0], b[nt * 2][1], b[nt * 2 + 1][0], b[nt * 2 + 1][1], bd);
        }
#pragma unroll
        for (int mi = 0; mi < 2; ++mi)
#pragma unroll
            for (int ni = 0; ni < 4; ++ni) mma16f(pc[mi][ni], a[mi], b[ni]);
    }

#pragma unroll
    for (int mi = 0; mi < 2; ++mi)
#pragma unroll
        for (int ni = 0; ni < 4; ++ni) {
            int row = nb * 128 + wy * 32 + mi * 16 + g;
            int col = nh * 64 + wx * 32 + ni * 8 + tig * 2;
            float bv0 = __ldg(b1 + col), bv1 = __ldg(b1 + col + 1);
            g_preds1[(size_t)row * CDIM + col]           = pc[mi][ni][0] + bv0;
            g_preds1[(size_t)row * CDIM + col + 1]       = pc[mi][ni][1] + bv1;
            g_preds1[(size_t)(row + 8) * CDIM + col]     = pc[mi][ni][2] + bv0;
            g_preds1[(size_t)(row + 8) * CDIM + col + 1] = pc[mi][ni][3] + bv1;
        }
}

__global__ void final_k(float* __restrict__ out) {
    out[0] = (float)(g_acc / (double)(LLOC * NTOK));
}

__global__ void __launch_bounds__(256, 2)      // <=128 regs -> 2 CTAs/SM with 88KB smem
main_k(const float* __restrict__ fmap_t,
       const float* __restrict__ fmap_tp1,
       const float* __restrict__ W2,
       const float* __restrict__ b2) {
    extern __shared__ char sm[];
    const uint32_t sbase = (uint32_t)__cvta_generic_to_shared(sm);
    const uint32_t sbA1 = sbase + OFF_A1, sbA2 = sbase + OFF_A2, sbB = sbase + OFF_B;
    float* rowS = reinterpret_cast<float*>(sm + OFF_ROWS);
    float* wred = reinterpret_cast<float*>(sm + OFF_WRED);

    const int l    = blockIdx.y;
    const int nb   = blockIdx.x;
    const int t    = threadIdx.x;
    const int lane = t & 31, warp = t >> 5;
    const int wy   = warp >> 1, wx = warp & 1;
    const int g    = lane >> 2, tig = lane & 3;

    const uint32_t aRow  = lane & 15;
    const uint32_t aKoff = ((lane >> 4) << 3);
    const uint32_t bRow  = ((lane >> 4) << 3) + (lane & 7);
    const uint32_t bKoff = (((lane >> 3) & 1) << 3);

    // ---------------- Phase 0: stage A1 (preds1) and A2 (loc) as fp16 ----------------
#pragma unroll
    for (int j = 0; j < 8; ++j) {
        int idx = j * 256 + t, row = idx >> 4, k0 = (idx & 15) * 8;
        stage8h(sm + OFF_A1, row, k0, g_preds1 + (size_t)(nb * 128 + row) * CDIM + k0);
        stage8h(sm + OFF_A2, row, k0,
                fmap_t + (size_t)(nb * 128 + row) * FSTRIDE + l * CDIM + k0);
    }
    rowS[t] = 0.f;
    __syncthreads();

    // ---------------- Phase 1: preds2 = loc @ W2^T + b2 (fp16 acc) ----------------
    uint32_t pc[2][2][4][2];
#pragma unroll
    for (int p = 0; p < 2; ++p)
#pragma unroll
        for (int mi = 0; mi < 2; ++mi)
#pragma unroll
            for (int ni = 0; ni < 4; ++ni) { pc[p][mi][ni][0] = 0u; pc[p][mi][ni][1] = 0u; }

#pragma unroll 1
    for (int p = 0; p < 2; ++p) {
        if (p) __syncthreads();
        {   // W2 rows [p*64, p*64+64) -> B tile
            int row = t >> 2, k0 = (t & 3) * 32;
            const float* src = W2 + (size_t)(p * 64 + row) * CDIM + k0;
#pragma unroll
            for (int j = 0; j < 4; ++j) stage8h(sm + OFF_B, row, k0 + j * 8, src + j * 8);
        }
        __syncthreads();

#pragma unroll
        for (int ks = 0; ks < 8; ++ks) {
            const int k0 = ks * 16;
            uint32_t a[2][4], b[4][2];
#pragma unroll
            for (int mi = 0; mi < 2; ++mi) {
                uint32_t ad = sbA2 + (wy * 32 + mi * 16 + aRow) * SKB + (k0 + aKoff) * 2;
                LDSM4(a[mi][0], a[mi][1], a[mi][2], a[mi][3], ad);
            }
#pragma unroll
            for (int nt = 0; nt < 2; ++nt) {
                uint32_t bd = sbB + (wx * 32 + nt * 16 + bRow) * SKB + (k0 + bKoff) * 2;
                LDSM4(b[nt * 2][0], b[nt * 2][1], b[nt * 2 + 1][0], b[nt * 2 + 1][1], bd);
            }
#pragma unroll
            for (int mi = 0; mi < 2; ++mi)
#pragma unroll
                for (int ni = 0; ni < 4; ++ni) mma16h(pc[p][mi][ni], a[mi], b[ni]);
        }
    }
    __syncthreads();                      // all reads of A2 (loc) complete

    // overwrite A2 with preds2 (+b2) as fp16
#pragma unroll
    for (int p = 0; p < 2; ++p)
#pragma unroll
        for (int mi = 0; mi < 2; ++mi)
#pragma unroll
            for (int ni = 0; ni < 4; ++ni) {
                int row = wy * 32 + mi * 16 + g;
                int col = p * 64 + wx * 32 + ni * 8 + tig * 2;
                float bv0 = __ldg(b2 + col), bv1 = __ldg(b2 + col + 1);
                float2 lo = up2(pc[p][mi][ni][0]), hi = up2(pc[p][mi][ni][1]);
                *reinterpret_cast<uint32_t*>(sm + OFF_A2 + row * SKB + col * 2) =
                    ph2(lo.x + bv0, lo.y + bv1);
                *reinterpret_cast<uint32_t*>(sm + OFF_A2 + (row + 8) * SKB + col * 2) =
                    ph2(hi.x + bv0, hi.y + bv1);
            }

    // ---------------- Phase 2: main loop over 8 pos chunks of 64 ----------------
    float S1[4] = {0.f, 0.f, 0.f, 0.f};
    float S2[4] = {0.f, 0.f, 0.f, 0.f};
    float diagAcc = 0.f;

    const int brow = t >> 2, bq = t & 3;
    const float* bsrc = fmap_tp1 + (size_t)brow * FSTRIDE + (size_t)l * CDIM + bq * 32;
    float4 pf[8];
    {
        const float4* p = reinterpret_cast<const float4*>(bsrc);
#pragma unroll
        for (int j = 0; j < 8; ++j) pf[j] = p[j];
    }

#pragma unroll 1
    for (int ch = 0; ch < 8; ++ch) {
        __syncthreads();                  // B tile free
        {
            char* dst = sm + OFF_B;
#pragma unroll
            for (int j = 0; j < 4; ++j) {
                float4 u = pf[2 * j], v = pf[2 * j + 1];
                uint4 w;
                w.x = ph2(u.x, u.y); w.y = ph2(u.z, u.w);
                w.z = ph2(v.x, v.y); w.w = ph2(v.z, v.w);
                *reinterpret_cast<uint4*>(dst + brow * SKB + (bq * 32 + j * 8) * 2) = w;
            }
        }
        __syncthreads();
        if (ch < 7) {
            const float4* p = reinterpret_cast<const float4*>(
                bsrc + (size_t)(ch + 1) * 64 * FSTRIDE);
#pragma unroll
            for (int j = 0; j < 8; ++j) pf[j] = p[j];
        }

        uint32_t c1[2][4][2], c2[2][4][2];
#pragma unroll
        for (int mi = 0; mi < 2; ++mi)
#pragma unroll
            for (int ni = 0; ni < 4; ++ni) {
                c1[mi][ni][0] = 0u; c1[mi][ni][1] = 0u;
                c2[mi][ni][0] = 0u; c2[mi][ni][1] = 0u;
            }

#pragma unroll
        for (int ks = 0; ks < 8; ++ks) {
            const int k0 = ks * 16;
            uint32_t a1f[2][4], a2f[2][4], b[4][2];
#pragma unroll
            for (int mi = 0; mi < 2; ++mi) {
                uint32_t off = (wy * 32 + mi * 16 + aRow) * SKB + (k0 + aKoff) * 2;
                LDSM4(a1f[mi][0], a1f[mi][1], a1f[mi][2], a1f[mi][3], sbA1 + off);
                LDSM4(a2f[mi][0], a2f[mi][1], a2f[mi][2], a2f[mi][3], sbA2 + off);
            }
#pragma unroll
            for (int nt = 0; nt < 2; ++nt) {
                uint32_t bd = sbB + (wx * 32 + nt * 16 + bRow) * SKB + (k0 + bKoff) * 2;
                LDSM4(b[nt * 2][0], b[nt * 2][1], b[nt * 2 + 1][0], b[nt * 2 + 1][1], bd);
            }
#pragma unroll
            for (int mi = 0; mi < 2; ++mi)
#pragma unroll
                for (int ni = 0; ni < 4; ++ni) {
                    mma16h(c1[mi][ni], a1f[mi], b[ni]);
                    mma16h(c2[mi][ni], a2f[mi], b[ni]);
                }
        }

        // fused epilogue: sum-exp + diag (|logit| < ~60 << 65504, no overflow)
#pragma unroll
        for (int mi = 0; mi < 2; ++mi) {
            const int r0 = nb * 128 + wy * 32 + mi * 16 + g;
            const int r1 = r0 + 8;
#pragma unroll
            for (int ni = 0; ni < 4; ++ni) {
                const int col = ch * 64 + wx * 32 + ni * 8 + tig * 2;
                float2 v1lo = up2(c1[mi][ni][0]), v1hi = up2(c1[mi][ni][1]);
                float2 v2lo = up2(c2[mi][ni][0]), v2hi = up2(c2[mi][ni][1]);
                S1[mi * 2 + 0] += __expf(v1lo.x) + __expf(v1lo.y);
                S1[mi * 2 + 1] += __expf(v1hi.x) + __expf(v1hi.y);
                S2[mi * 2 + 0] += __expf(v2lo.x) + __expf(v2lo.y);
                S2[mi * 2 + 1] += __expf(v2hi.x) + __expf(v2hi.y);
                if (col     == r0) diagAcc += v1lo.x + v2lo.x;
                if (col + 1 == r0) diagAcc += v1lo.y + v2lo.y;
                if (col     == r1) diagAcc += v1hi.x + v2hi.x;
                if (col + 1 == r1) diagAcc += v1hi.y + v2hi.y;
            }
        }
    }

    // ---------------- Phase 3: reductions ----------------
#pragma unroll
    for (int slot = 0; slot < 4; ++slot) {
        float s1 = S1[slot], s2 = S2[slot];
        s1 += __shfl_xor_sync(0xffffffffu, s1, 1);
        s1 += __shfl_xor_sync(0xffffffffu, s1, 2);
        s2 += __shfl_xor_sync(0xffffffffu, s2, 1);
        s2 += __shfl_xor_sync(0xffffffffu, s2, 2);
        if (tig == 0) {
            int row = wy * 32 + (slot >> 1) * 16 + g + (slot & 1) * 8;
            atomicAdd(&rowS[row], s1);
            atomicAdd(&rowS[128 + row], s2);
        }
    }
    __syncthreads();

    float contrib = -diagAcc + __logf(rowS[t]);
#pragma unroll
    for (int off = 16; off > 0; off >>= 1)
        contrib += __shfl_down_sync(0xffffffffu, contrib, off);
    if (lane == 0) wred[warp] = contrib;
    __syncthreads();
    if (t == 0) {
        float v = 0.f;
#pragma unroll
        for (int w = 0; w < 8; ++w) v += wred[w];
        atomicAdd(&g_acc, (double)v);
    }
}

extern "C" void kernel_launch(void* const* d_in, const int* in_sizes, int n_in,
                              void* d_out, int out_size) {
    const float* f_t      = (const float*)d_in[0];
    const float* fmap_t   = (const float*)d_in[1];
    const float* fmap_tp1 = (const float*)d_in[2];
    const float* W1       = (const float*)d_in[3];
    const float* b1       = (const float*)d_in[4];
    const float* W2       = (const float*)d_in[5];
    const float* b2       = (const float*)d_in[6];
    float* out = (float*)d_out;

    cudaFuncSetAttribute(preds1_k, cudaFuncAttributeMaxDynamicSharedMemorySize, P_SMEM);
    cudaFuncSetAttribute(main_k, cudaFuncAttributeMaxDynamicSharedMemorySize, SMEM_TOTAL);

    dim3 pgrid(NTOK / 128, 2);     // (4, 2)
    preds1_k<<<pgrid, 256, P_SMEM>>>(f_t, W1, b1);
    dim3 grid(NTOK / 128, LLOC);   // (4, 144)
    main_k<<<grid, 256, SMEM_TOTAL>>>(fmap_t, fmap_tp1, W2, b2);
    final_k<<<1, 1>>>(out);
}

// round 12
// speedup vs baseline: 2.9387x; 1.0799x over previous
#include <cuda_runtime.h>
#include <cuda_fp16.h>
#include <cstdint>

#define NTOK 512
#define CDIM 128
#define LLOC 144
#define DDIM 256
#define FSTRIDE (LLOC * CDIM)
#define SKB 272                   // main_k smem row stride (bytes, 136 halves)
#define PKB 528                   // preds1_k smem row stride
#define LOG2E 1.4426950408889634f
#define LN2   0.6931471805599453f
#define FMAPN (NTOK * LLOC * CDIM)   // 9437184 elements

// main_k smem byte offsets
#define OFF_A1   0
#define OFF_A2   34816
#define OFF_B0   69632
#define OFF_B1   87040
#define OFF_ROWS 104448           // 256 floats
#define OFF_WRED 105472           // 8 floats
#define SMEM_TOTAL 105504         // x2 = 211008 < 227KB -> 2 CTAs/SM
// preds1_k smem
#define P_OFF_B  67584
#define P_SMEM   101376

__device__ __half g_loch[FMAPN];     // fmap_t * log2e, fp16
__device__ __half g_posh[FMAPN];     // fmap_tp1, fp16
__device__ __half g_p1h[NTOK * CDIM];// preds1 * log2e, fp16
__device__ double g_acc;
__device__ unsigned int g_done;

__device__ __forceinline__ uint32_t ph2(float x, float y) {
    __half2 h = __floats2half2_rn(x, y);
    return *reinterpret_cast<uint32_t*>(&h);
}
__device__ __forceinline__ float2 up2(uint32_t v) {
    return __half22float2(*reinterpret_cast<__half2*>(&v));
}
__device__ __forceinline__ float ex2f(float x) {
    float r; asm("ex2.approx.f32 %0, %1;" : "=f"(r) : "f"(x)); return r;
}
__device__ __forceinline__ void cpa16(uint32_t dst, const void* src) {
    asm volatile("cp.async.cg.shared.global [%0], [%1], 16;"
                 :: "r"(dst), "l"(src) : "memory");
}
#define CP_COMMIT() asm volatile("cp.async.commit_group;" ::: "memory")
#define CP_WAIT(n)  asm volatile("cp.async.wait_group %0;" :: "n"(n) : "memory")

__device__ __forceinline__ void stage8h(char* tile, int row, int k0,
                                        const float* __restrict__ src) {
    float4 a = *reinterpret_cast<const float4*>(src);
    float4 b = *reinterpret_cast<const float4*>(src + 4);
    uint4 v;
    v.x = ph2(a.x, a.y); v.y = ph2(a.z, a.w);
    v.z = ph2(b.x, b.y); v.w = ph2(b.z, b.w);
    *reinterpret_cast<uint4*>(tile + row * SKB + k0 * 2) = v;
}

#define LDSM4(r0, r1, r2, r3, addr) \
    asm volatile("ldmatrix.sync.aligned.m8n8.x4.shared.b16 {%0,%1,%2,%3}, [%4];" \
                 : "=r"(r0), "=r"(r1), "=r"(r2), "=r"(r3) : "r"(addr))

__device__ __forceinline__ void mma16h(uint32_t* c, const uint32_t* a, const uint32_t* b) {
    asm volatile(
        "mma.sync.aligned.m16n8k16.row.col.f16.f16.f16.f16 "
        "{%0,%1}, {%2,%3,%4,%5}, {%6,%7}, {%0,%1};\n"
        : "+r"(c[0]), "+r"(c[1])
        : "r"(a[0]), "r"(a[1]), "r"(a[2]), "r"(a[3]), "r"(b[0]), "r"(b[1]));
}
__device__ __forceinline__ void mma16f(float* c, const uint32_t* a, const uint32_t* b) {
    asm volatile(
        "mma.sync.aligned.m16n8k16.row.col.f32.f16.f16.f32 "
        "{%0,%1,%2,%3}, {%4,%5,%6,%7}, {%8,%9}, {%0,%1,%2,%3};\n"
        : "+f"(c[0]), "+f"(c[1]), "+f"(c[2]), "+f"(c[3])
        : "r"(a[0]), "r"(a[1]), "r"(a[2]), "r"(a[3]), "r"(b[0]), "r"(b[1]));
}

// ---- prep: fp32 fmaps -> fp16 (loc scaled by log2e) ----
__global__ void __launch_bounds__(256, 4)
prep_k(const float* __restrict__ fmap_t, const float* __restrict__ fmap_tp1) {
    const int which = blockIdx.y;
    const float s = which ? 1.0f : LOG2E;
    const float* src = which ? fmap_tp1 : fmap_t;
    __half* dst = which ? g_posh : g_loch;
    size_t i = ((size_t)blockIdx.x * 256 + threadIdx.x) * 8;
    float4 a = *reinterpret_cast<const float4*>(src + i);
    float4 b = *reinterpret_cast<const float4*>(src + i + 4);
    uint4 v;
    v.x = ph2(a.x * s, a.y * s); v.y = ph2(a.z * s, a.w * s);
    v.z = ph2(b.x * s, b.y * s); v.w = ph2(b.z * s, b.w * s);
    *reinterpret_cast<uint4*>(dst + i) = v;
}

// ---- preds1 = (f_t @ W1^T + b1) * log2e -> fp16; grid (4,2) ----
__global__ void __launch_bounds__(256, 2)
preds1_k(const float* __restrict__ f_t,
         const float* __restrict__ W1,
         const float* __restrict__ b1) {
    extern __shared__ char psm[];
    const uint32_t sb = (uint32_t)__cvta_generic_to_shared(psm);
    const int nb = blockIdx.x, nh = blockIdx.y;
    const int t = threadIdx.x, lane = t & 31, warp = t >> 5;
    const int wy = warp >> 1, wx = warp & 1;
    const int g = lane >> 2, tig = lane & 3;
    if (nb == 0 && nh == 0 && t == 0) g_acc = 0.0;

    {   // stage A rows (f_t slab)
        int row = t >> 1, half = t & 1;
        const float4* sa = reinterpret_cast<const float4*>(
            f_t + (size_t)(nb * 128 + row) * DDIM + half * 128);
        uint2* da = reinterpret_cast<uint2*>(psm + row * PKB + half * 256);
#pragma unroll
        for (int j = 0; j < 32; ++j) {
            float4 a = sa[j];
            da[j] = make_uint2(ph2(a.x, a.y), ph2(a.z, a.w));
        }
    }
    {   // stage B rows (W1 slice, 64 rows)
        int row = t >> 2, q = t & 3;
        const float4* sw = reinterpret_cast<const float4*>(
            W1 + (size_t)(nh * 64 + row) * DDIM + q * 64);
        uint2* dw = reinterpret_cast<uint2*>(psm + P_OFF_B + row * PKB + q * 128);
#pragma unroll
        for (int j = 0; j < 16; ++j) {
            float4 w = sw[j];
            dw[j] = make_uint2(ph2(w.x, w.y), ph2(w.z, w.w));
        }
    }
    __syncthreads();

    const uint32_t aRow = lane & 15, aKoff = ((lane >> 4) << 3);
    const uint32_t bRow = ((lane >> 4) << 3) + (lane & 7), bKoff = (((lane >> 3) & 1) << 3);

    float pc[2][4][4];
#pragma unroll
    for (int mi = 0; mi < 2; ++mi)
#pragma unroll
        for (int ni = 0; ni < 4; ++ni)
#pragma unroll
            for (int q = 0; q < 4; ++q) pc[mi][ni][q] = 0.f;

#pragma unroll 2
    for (int ks = 0; ks < 16; ++ks) {
        const int k0 = ks * 16;
        uint32_t a[2][4], b[4][2];
#pragma unroll
        for (int mi = 0; mi < 2; ++mi) {
            uint32_t ad = sb + (wy * 32 + mi * 16 + aRow) * PKB + (k0 + aKoff) * 2;
            LDSM4(a[mi][0], a[mi][1], a[mi][2], a[mi][3], ad);
        }
#pragma unroll
        for (int nt = 0; nt < 2; ++nt) {
            uint32_t bd = sb + P_OFF_B + (wx * 32 + nt * 16 + bRow) * PKB + (k0 + bKoff) * 2;
            LDSM4(b[nt * 2][0], b[nt * 2][1], b[nt * 2 + 1][0], b[nt * 2 + 1][1], bd);
        }
#pragma unroll
        for (int mi = 0; mi < 2; ++mi)
#pragma unroll
            for (int ni = 0; ni < 4; ++ni) mma16f(pc[mi][ni], a[mi], b[ni]);
    }

#pragma unroll
    for (int mi = 0; mi < 2; ++mi)
#pragma unroll
        for (int ni = 0; ni < 4; ++ni) {
            int row = nb * 128 + wy * 32 + mi * 16 + g;
            int col = nh * 64 + wx * 32 + ni * 8 + tig * 2;
            float bv0 = __ldg(b1 + col), bv1 = __ldg(b1 + col + 1);
            *reinterpret_cast<uint32_t*>(&g_p1h[(size_t)row * CDIM + col]) =
                ph2((pc[mi][ni][0] + bv0) * LOG2E, (pc[mi][ni][1] + bv1) * LOG2E);
            *reinterpret_cast<uint32_t*>(&g_p1h[(size_t)(row + 8) * CDIM + col]) =
                ph2((pc[mi][ni][2] + bv0) * LOG2E, (pc[mi][ni][3] + bv1) * LOG2E);
        }
}

__global__ void __launch_bounds__(256, 2)
main_k(const float* __restrict__ W2,
       const float* __restrict__ b2,
       float* __restrict__ out) {
    extern __shared__ char sm[];
    const uint32_t sbase = (uint32_t)__cvta_generic_to_shared(sm);
    const uint32_t sbA1 = sbase + OFF_A1, sbA2 = sbase + OFF_A2;
    float* rowS = reinterpret_cast<float*>(sm + OFF_ROWS);
    float* wred = reinterpret_cast<float*>(sm + OFF_WRED);

    const int l    = blockIdx.y;
    const int nb   = blockIdx.x;
    const int t    = threadIdx.x;
    const int lane = t & 31, warp = t >> 5;
    const int wy   = warp >> 1, wx = warp & 1;
    const int g    = lane >> 2, tig = lane & 3;

    const uint32_t aRow  = lane & 15;
    const uint32_t aKoff = ((lane >> 4) << 3);
    const uint32_t bRow  = ((lane >> 4) << 3) + (lane & 7);
    const uint32_t bKoff = (((lane >> 3) & 1) << 3);

    // ---- Phase 0: cp.async A1 (preds1*log2e) and A2 (loc*log2e); stage W2 ----
#pragma unroll
    for (int j = 0; j < 8; ++j) {
        int idx = j * 256 + t, row = idx >> 4, piece = idx & 15;
        cpa16(sbA1 + row * SKB + piece * 16,
              g_p1h + (size_t)(nb * 128 + row) * CDIM + piece * 8);
        cpa16(sbA2 + row * SKB + piece * 16,
              g_loch + (size_t)(nb * 128 + row) * FSTRIDE + l * CDIM + piece * 8);
    }
    CP_COMMIT();
    {   // W2: rows 0-63 -> B0, rows 64-127 -> B1 (fp32->fp16 cvt path)
        int row = t >> 2, k0 = (t & 3) * 32;
#pragma unroll
        for (int j = 0; j < 4; ++j) {
            stage8h(sm + OFF_B0, row, k0 + j * 8, W2 + (size_t)row * CDIM + k0 + j * 8);
            stage8h(sm + OFF_B1, row, k0 + j * 8,
                    W2 + (size_t)(64 + row) * CDIM + k0 + j * 8);
        }
    }
    rowS[t] = 0.f;
    CP_WAIT(0);
    __syncthreads();

    // ---- Phase 1: preds2 = loc @ W2^T (scaled); both halves pre-staged ----
    uint32_t pc[2][2][4][2];
#pragma unroll
    for (int p = 0; p < 2; ++p)
#pragma unroll
        for (int mi = 0; mi < 2; ++mi)
#pragma unroll
            for (int ni = 0; ni < 4; ++ni) { pc[p][mi][ni][0] = 0u; pc[p][mi][ni][1] = 0u; }

#pragma unroll 1
    for (int p = 0; p < 2; ++p) {
        const uint32_t sbB = sbase + (p ? OFF_B1 : OFF_B0);
#pragma unroll
        for (int ks = 0; ks < 8; ++ks) {
            const int k0 = ks * 16;
            uint32_t a[2][4], b[4][2];
#pragma unroll
            for (int mi = 0; mi < 2; ++mi) {
                uint32_t ad = sbA2 + (wy * 32 + mi * 16 + aRow) * SKB + (k0 + aKoff) * 2;
                LDSM4(a[mi][0], a[mi][1], a[mi][2], a[mi][3], ad);
            }
#pragma unroll
            for (int nt = 0; nt < 2; ++nt) {
                uint32_t bd = sbB + (wx * 32 + nt * 16 + bRow) * SKB + (k0 + bKoff) * 2;
                LDSM4(b[nt * 2][0], b[nt * 2][1], b[nt * 2 + 1][0], b[nt * 2 + 1][1], bd);
            }
#pragma unroll
            for (int mi = 0; mi < 2; ++mi)
#pragma unroll
                for (int ni = 0; ni < 4; ++ni) mma16h(pc[p][mi][ni], a[mi], b[ni]);
        }
    }
    __syncthreads();                      // all reads of A2 (loc) and B0/B1 (W2) done

    // overwrite A2 with preds2 (+b2*log2e); kick off pos chunks 0,1 via cp.async
#pragma unroll
    for (int p = 0; p < 2; ++p)
#pragma unroll
        for (int mi = 0; mi < 2; ++mi)
#pragma unroll
            for (int ni = 0; ni < 4; ++ni) {
                int row = wy * 32 + mi * 16 + g;
                int col = p * 64 + wx * 32 + ni * 8 + tig * 2;
                float bv0 = __ldg(b2 + col) * LOG2E, bv1 = __ldg(b2 + col + 1) * LOG2E;
                float2 lo = up2(pc[p][mi][ni][0]), hi = up2(pc[p][mi][ni][1]);
                *reinterpret_cast<uint32_t*>(sm + OFF_A2 + row * SKB + col * 2) =
                    ph2(lo.x + bv0, lo.y + bv1);
                *reinterpret_cast<uint32_t*>(sm + OFF_A2 + (row + 8) * SKB + col * 2) =
                    ph2(hi.x + bv0, hi.y + bv1);
            }
#pragma unroll
    for (int j = 0; j < 4; ++j) {         // chunk 0 -> B0
        int idx = j * 256 + t, row = idx >> 4, piece = idx & 15;
        cpa16(sbase + OFF_B0 + row * SKB + piece * 16,
              g_posh + (size_t)row * FSTRIDE + l * CDIM + piece * 8);
    }
    CP_COMMIT();
#pragma unroll
    for (int j = 0; j < 4; ++j) {         // chunk 1 -> B1
        int idx = j * 256 + t, row = idx >> 4, piece = idx & 15;
        cpa16(sbase + OFF_B1 + row * SKB + piece * 16,
              g_posh + (size_t)(64 + row) * FSTRIDE + l * CDIM + piece * 8);
    }
    CP_COMMIT();
    __syncthreads();                      // preds2 writes visible

    // ---- Phase 2: 8 pos chunks of 64, double-buffered B via cp.async ----
    float S1[4] = {0.f, 0.f, 0.f, 0.f};
    float S2[4] = {0.f, 0.f, 0.f, 0.f};
    float diagAcc = 0.f;

#pragma unroll 1
    for (int ch = 0; ch < 8; ++ch) {
        const int buf = ch & 1;
        const uint32_t sbB = sbase + (buf ? OFF_B1 : OFF_B0);
        CP_WAIT(1);                       // chunk ch landed (FIFO group completion)
        __syncthreads();

        uint32_t c1[2][4][2], c2[2][4][2];
#pragma unroll
        for (int mi = 0; mi < 2; ++mi)
#pragma unroll
            for (int ni = 0; ni < 4; ++ni) {
                c1[mi][ni][0] = 0u; c1[mi][ni][1] = 0u;
                c2[mi][ni][0] = 0u; c2[mi][ni][1] = 0u;
            }

#pragma unroll
        for (int ks = 0; ks < 8; ++ks) {
            const int k0 = ks * 16;
            uint32_t a1f[2][4], a2f[2][4], b[4][2];
#pragma unroll
            for (int mi = 0; mi < 2; ++mi) {
                uint32_t off = (wy * 32 + mi * 16 + aRow) * SKB + (k0 + aKoff) * 2;
                LDSM4(a1f[mi][0], a1f[mi][1], a1f[mi][2], a1f[mi][3], sbA1 + off);
                LDSM4(a2f[mi][0], a2f[mi][1], a2f[mi][2], a2f[mi][3], sbA2 + off);
            }
#pragma unroll
            for (int nt = 0; nt < 2; ++nt) {
                uint32_t bd = sbB + (wx * 32 + nt * 16 + bRow) * SKB + (k0 + bKoff) * 2;
                LDSM4(b[nt * 2][0], b[nt * 2][1], b[nt * 2 + 1][0], b[nt * 2 + 1][1], bd);
            }
#pragma unroll
            for (int mi = 0; mi < 2; ++mi)
#pragma unroll
                for (int ni = 0; ni < 4; ++ni) {
                    mma16h(c1[mi][ni], a1f[mi], b[ni]);
                    mma16h(c2[mi][ni], a2f[mi], b[ni]);
                }
        }
        __syncthreads();                  // all warps done reading B[buf]

        if (ch < 6) {                     // chunk ch+2 -> B[buf]
#pragma unroll
            for (int j = 0; j < 4; ++j) {
                int idx = j * 256 + t, row = idx >> 4, piece = idx & 15;
                cpa16(sbB + row * SKB + piece * 16,
                      g_posh + (size_t)((ch + 2) * 64 + row) * FSTRIDE + l * CDIM + piece * 8);
            }
        }
        CP_COMMIT();                      // (empty group for ch>=6: keeps FIFO count)

        // epilogue (registers only): logits are log2-scaled -> raw ex2
#pragma unroll
        for (int mi = 0; mi < 2; ++mi) {
            const int r0 = nb * 128 + wy * 32 + mi * 16 + g;
            const int r1 = r0 + 8;
#pragma unroll
            for (int ni = 0; ni < 4; ++ni) {
                const int col = ch * 64 + wx * 32 + ni * 8 + tig * 2;
                float2 v1lo = up2(c1[mi][ni][0]), v1hi = up2(c1[mi][ni][1]);
                float2 v2lo = up2(c2[mi][ni][0]), v2hi = up2(c2[mi][ni][1]);
                S1[mi * 2 + 0] += ex2f(v1lo.x) + ex2f(v1lo.y);
                S1[mi * 2 + 1] += ex2f(v1hi.x) + ex2f(v1hi.y);
                S2[mi * 2 + 0] += ex2f(v2lo.x) + ex2f(v2lo.y);
                S2[mi * 2 + 1] += ex2f(v2hi.x) + ex2f(v2hi.y);
                if (col     == r0) diagAcc += v1lo.x + v2lo.x;
                if (col + 1 == r0) diagAcc += v1lo.y + v2lo.y;
                if (col     == r1) diagAcc += v1hi.x + v2hi.x;
                if (col + 1 == r1) diagAcc += v1hi.y + v2hi.y;
            }
        }
    }

    // ---- Phase 3: reductions + fused finalize ----
#pragma unroll
    for (int slot = 0; slot < 4; ++slot) {
        float s1 = S1[slot], s2 = S2[slot];
        s1 += __shfl_xor_sync(0xffffffffu, s1, 1);
        s1 += __shfl_xor_sync(0xffffffffu, s1, 2);
        s2 += __shfl_xor_sync(0xffffffffu, s2, 1);
        s2 += __shfl_xor_sync(0xffffffffu, s2, 2);
        if (tig == 0) {
            int row = wy * 32 + (slot >> 1) * 16 + g + (slot & 1) * 8;
            atomicAdd(&rowS[row], s1);
            atomicAdd(&rowS[128 + row], s2);
        }
    }
    __syncthreads();

    float contrib = -diagAcc * LN2 + __logf(rowS[t]);
#pragma unroll
    for (int off = 16; off > 0; off >>= 1)
        contrib += __shfl_down_sync(0xffffffffu, contrib, off);
    if (lane == 0) wred[warp] = contrib;
    __syncthreads();
    if (t == 0) {
        float v = 0.f;
#pragma unroll
        for (int w = 0; w < 8; ++w) v += wred[w];
        atomicAdd(&g_acc, (double)v);
        __threadfence();
        unsigned fin = atomicAdd(&g_done, 1u);
        if (fin == (unsigned)(4 * LLOC - 1)) {
            out[0] = (float)(g_acc / (double)(LLOC * NTOK));
            g_done = 0;
            g_acc = 0.0;
        }
    }
}

extern "C" void kernel_launch(void* const* d_in, const int* in_sizes, int n_in,
                              void* d_out, int out_size) {
    const float* f_t      = (const float*)d_in[0];
    const float* fmap_t   = (const float*)d_in[1];
    const float* fmap_tp1 = (const float*)d_in[2];
    const float* W1       = (const float*)d_in[3];
    const float* b1       = (const float*)d_in[4];
    const float* W2       = (const float*)d_in[5];
    const float* b2       = (const float*)d_in[6];
    float* out = (float*)d_out;

    cudaFuncSetAttribute(preds1_k, cudaFuncAttributeMaxDynamicSharedMemorySize, P_SMEM);
    cudaFuncSetAttribute(main_k, cudaFuncAttributeMaxDynamicSharedMemorySize, SMEM_TOTAL);

    dim3 cgrid(FMAPN / (256 * 8), 2);    // (4608, 2)
    prep_k<<<cgrid, 256>>>(fmap_t, fmap_tp1);
    dim3 pgrid(NTOK / 128, 2);           // (4, 2)
    preds1_k<<<pgrid, 256, P_SMEM>>>(f_t, W1, b1);
    dim3 grid(NTOK / 128, LLOC);         // (4, 144)
    main_k<<<grid, 256, SMEM_TOTAL>>>(W2, b2, out);
}

// round 14
// speedup vs baseline: 4.7182x; 1.6055x over previous
#include <cuda_runtime.h>
#include <cuda_fp16.h>
#include <cstdint>

#define NTOK 512
#define CDIM 128
#define LLOC 144
#define DDIM 256
#define FSTRIDE (LLOC * CDIM)
#define SKB 272                   // main_k smem row stride (bytes, 136 halves)
#define PKB 528                   // setup GEMM smem row stride
#define LOG2E 1.4426950408889634f
#define LN2   0.6931471805599453f
#define FMAPN (NTOK * LLOC * CDIM)   // 9437184 elements
#define CONVB (FMAPN / 2048)         // 4608 conversion blocks

// main_k smem byte offsets
#define OFF_A1   0
#define OFF_A2   34816
#define OFF_B0   69632
#define OFF_B1   87040
#define OFF_ROWS 104448           // 256 floats
#define OFF_WRED 105472           // 8 floats
#define SMEM_TOTAL 105504         // x2 = 211008 < 227KB -> 2 CTAs/SM
// setup_k smem (preds1 GEMM blocks)
#define P_OFF_B  67584
#define P_SMEM   101376

__device__ __half g_posh[FMAPN];      // fmap_tp1, fp16
__device__ __half g_p1h[NTOK * CDIM]; // preds1 * log2e, fp16
__device__ double g_acc;
__device__ unsigned int g_done;

__device__ __forceinline__ uint32_t ph2(float x, float y) {
    __half2 h = __floats2half2_rn(x, y);
    return *reinterpret_cast<uint32_t*>(&h);
}
__device__ __forceinline__ float2 up2(uint32_t v) {
    return __half22float2(*reinterpret_cast<__half2*>(&v));
}
__device__ __forceinline__ float ex2f(float x) {
    float r; asm("ex2.approx.f32 %0, %1;" : "=f"(r) : "f"(x)); return r;
}
__device__ __forceinline__ void cpa16(uint32_t dst, const void* src) {
    asm volatile("cp.async.cg.shared.global [%0], [%1], 16;"
                 :: "r"(dst), "l"(src) : "memory");
}
#define CP_COMMIT() asm volatile("cp.async.commit_group;" ::: "memory")
#define CP_WAIT(n)  asm volatile("cp.async.wait_group %0;" :: "n"(n) : "memory")

__device__ __forceinline__ void stage8h(char* tile, int row, int k0,
                                        const float* __restrict__ src) {
    float4 a = *reinterpret_cast<const float4*>(src);
    float4 b = *reinterpret_cast<const float4*>(src + 4);
    uint4 v;
    v.x = ph2(a.x, a.y); v.y = ph2(a.z, a.w);
    v.z = ph2(b.x, b.y); v.w = ph2(b.z, b.w);
    *reinterpret_cast<uint4*>(tile + row * SKB + k0 * 2) = v;
}
__device__ __forceinline__ void stage8hs(char* tile, int row, int k0,
                                         const float* __restrict__ src, float s) {
    float4 a = *reinterpret_cast<const float4*>(src);
    float4 b = *reinterpret_cast<const float4*>(src + 4);
    uint4 v;
    v.x = ph2(a.x * s, a.y * s); v.y = ph2(a.z * s, a.w * s);
    v.z = ph2(b.x * s, b.y * s); v.w = ph2(b.z * s, b.w * s);
    *reinterpret_cast<uint4*>(tile + row * SKB + k0 * 2) = v;
}

#define LDSM4(r0, r1, r2, r3, addr) \
    asm volatile("ldmatrix.sync.aligned.m8n8.x4.shared.b16 {%0,%1,%2,%3}, [%4];" \
                 : "=r"(r0), "=r"(r1), "=r"(r2), "=r"(r3) : "r"(addr))

__device__ __forceinline__ void mma16h(uint32_t* c, const uint32_t* a, const uint32_t* b) {
    asm volatile(
        "mma.sync.aligned.m16n8k16.row.col.f16.f16.f16.f16 "
        "{%0,%1}, {%2,%3,%4,%5}, {%6,%7}, {%0,%1};\n"
        : "+r"(c[0]), "+r"(c[1])
        : "r"(a[0]), "r"(a[1]), "r"(a[2]), "r"(a[3]), "r"(b[0]), "r"(b[1]));
}
__device__ __forceinline__ void mma16f(float* c, const uint32_t* a, const uint32_t* b) {
    asm volatile(
        "mma.sync.aligned.m16n8k16.row.col.f32.f16.f16.f32 "
        "{%0,%1,%2,%3}, {%4,%5,%6,%7}, {%8,%9}, {%0,%1,%2,%3};\n"
        : "+f"(c[0]), "+f"(c[1]), "+f"(c[2]), "+f"(c[3])
        : "r"(a[0]), "r"(a[1]), "r"(a[2]), "r"(a[3]), "r"(b[0]), "r"(b[1]));
}

// ---- setup: blocks 0-7 = preds1 GEMM; blocks 8.. = pos fp32->fp16 conversion ----
__global__ void __launch_bounds__(256, 2)
setup_k(const float* __restrict__ f_t,
        const float* __restrict__ W1,
        const float* __restrict__ b1,
        const float* __restrict__ fmap_tp1) {
    const int t = threadIdx.x;
    if (blockIdx.x >= 8) {
        // conversion path: no smem use
        size_t i = ((size_t)(blockIdx.x - 8) * 256 + t) * 8;
        float4 a = *reinterpret_cast<const float4*>(fmap_tp1 + i);
        float4 b = *reinterpret_cast<const float4*>(fmap_tp1 + i + 4);
        uint4 v;
        v.x = ph2(a.x, a.y); v.y = ph2(a.z, a.w);
        v.z = ph2(b.x, b.y); v.w = ph2(b.z, b.w);
        *reinterpret_cast<uint4*>(g_posh + i) = v;
        return;
    }

    // preds1 path: preds1 = (f_t @ W1^T + b1) * log2e -> g_p1h
    extern __shared__ char psm[];
    const uint32_t sb = (uint32_t)__cvta_generic_to_shared(psm);
    const int nb = blockIdx.x & 3, nh = blockIdx.x >> 2;
    const int lane = t & 31, warp = t >> 5;
    const int wy = warp >> 1, wx = warp & 1;
    const int g = lane >> 2, tig = lane & 3;
    if (blockIdx.x == 0 && t == 0) g_acc = 0.0;

    {   // stage A rows (f_t slab)
        int row = t >> 1, half = t & 1;
        const float4* sa = reinterpret_cast<const float4*>(
            f_t + (size_t)(nb * 128 + row) * DDIM + half * 128);
        uint2* da = reinterpret_cast<uint2*>(psm + row * PKB + half * 256);
#pragma unroll
        for (int j = 0; j < 32; ++j) {
            float4 a = sa[j];
            da[j] = make_uint2(ph2(a.x, a.y), ph2(a.z, a.w));
        }
    }
    {   // stage B rows (W1 slice, 64 rows)
        int row = t >> 2, q = t & 3;
        const float4* sw = reinterpret_cast<const float4*>(
            W1 + (size_t)(nh * 64 + row) * DDIM + q * 64);
        uint2* dw = reinterpret_cast<uint2*>(psm + P_OFF_B + row * PKB + q * 128);
#pragma unroll
        for (int j = 0; j < 16; ++j) {
            float4 w = sw[j];
            dw[j] = make_uint2(ph2(w.x, w.y), ph2(w.z, w.w));
        }
    }
    __syncthreads();

    const uint32_t aRow = lane & 15, aKoff = ((lane >> 4) << 3);
    const uint32_t bRow = ((lane >> 4) << 3) + (lane & 7), bKoff = (((lane >> 3) & 1) << 3);

    float pc[2][4][4];
#pragma unroll
    for (int mi = 0; mi < 2; ++mi)
#pragma unroll
        for (int ni = 0; ni < 4; ++ni)
#pragma unroll
            for (int q = 0; q < 4; ++q) pc[mi][ni][q] = 0.f;

#pragma unroll 2
    for (int ks = 0; ks < 16; ++ks) {
        const int k0 = ks * 16;
        uint32_t a[2][4], b[4][2];
#pragma unroll
        for (int mi = 0; mi < 2; ++mi) {
            uint32_t ad = sb + (wy * 32 + mi * 16 + aRow) * PKB + (k0 + aKoff) * 2;
            LDSM4(a[mi][0], a[mi][1], a[mi][2], a[mi][3], ad);
        }
#pragma unroll
        for (int nt = 0; nt < 2; ++nt) {
            uint32_t bd = sb + P_OFF_B + (wx * 32 + nt * 16 + bRow) * PKB + (k0 + bKoff) * 2;
            LDSM4(b[nt * 2][0], b[nt * 2][1], b[nt * 2 + 1][0], b[nt * 2 + 1][1], bd);
        }
#pragma unroll
        for (int mi = 0; mi < 2; ++mi)
#pragma unroll
            for (int ni = 0; ni < 4; ++ni) mma16f(pc[mi][ni], a[mi], b[ni]);
    }

#pragma unroll
    for (int mi = 0; mi < 2; ++mi)
#pragma unroll
        for (int ni = 0; ni < 4; ++ni) {
            int row = nb * 128 + wy * 32 + mi * 16 + g;
            int col = nh * 64 + wx * 32 + ni * 8 + tig * 2;
            float bv0 = __ldg(b1 + col), bv1 = __ldg(b1 + col + 1);
            *reinterpret_cast<uint32_t*>(&g_p1h[(size_t)row * CDIM + col]) =
                ph2((pc[mi][ni][0] + bv0) * LOG2E, (pc[mi][ni][1] + bv1) * LOG2E);
            *reinterpret_cast<uint32_t*>(&g_p1h[(size_t)(row + 8) * CDIM + col]) =
                ph2((pc[mi][ni][2] + bv0) * LOG2E, (pc[mi][ni][3] + bv1) * LOG2E);
        }
}

__global__ void __launch_bounds__(256, 2)
main_k(const float* __restrict__ fmap_t,
       const float* __restrict__ W2,
       const float* __restrict__ b2,
       float* __restrict__ out) {
    extern __shared__ char sm[];
    const uint32_t sbase = (uint32_t)__cvta_generic_to_shared(sm);
    const uint32_t sbA1 = sbase + OFF_A1, sbA2 = sbase + OFF_A2;
    float* rowS = reinterpret_cast<float*>(sm + OFF_ROWS);
    float* wred = reinterpret_cast<float*>(sm + OFF_WRED);

    const int l    = blockIdx.y;
    const int nb   = blockIdx.x;
    const int t    = threadIdx.x;
    const int lane = t & 31, warp = t >> 5;
    const int wy   = warp >> 1, wx = warp & 1;
    const int g    = lane >> 2, tig = lane & 3;

    const uint32_t aRow  = lane & 15;
    const uint32_t aKoff = ((lane >> 4) << 3);
    const uint32_t bRow  = ((lane >> 4) << 3) + (lane & 7);
    const uint32_t bKoff = (((lane >> 3) & 1) << 3);

    // ---- Phase 0: cp.async A1 (preds1*log2e); loc fp32->fp16; W2*log2e ----
#pragma unroll
    for (int j = 0; j < 8; ++j) {
        int idx = j * 256 + t, row = idx >> 4, piece = idx & 15;
        cpa16(sbA1 + row * SKB + piece * 16,
              g_p1h + (size_t)(nb * 128 + row) * CDIM + piece * 8);
    }
    CP_COMMIT();
#pragma unroll
    for (int j = 0; j < 8; ++j) {   // loc (unscaled; log2e lives in W2/preds1)
        int idx = j * 256 + t, row = idx >> 4, k0 = (idx & 15) * 8;
        stage8h(sm + OFF_A2, row, k0,
                fmap_t + (size_t)(nb * 128 + row) * FSTRIDE + l * CDIM + k0);
    }
    {   // W2 * log2e: rows 0-63 -> B0, rows 64-127 -> B1
        int row = t >> 2, k0 = (t & 3) * 32;
#pragma unroll
        for (int j = 0; j < 4; ++j) {
            stage8hs(sm + OFF_B0, row, k0 + j * 8,
                     W2 + (size_t)row * CDIM + k0 + j * 8, LOG2E);
            stage8hs(sm + OFF_B1, row, k0 + j * 8,
                     W2 + (size_t)(64 + row) * CDIM + k0 + j * 8, LOG2E);
        }
    }
    rowS[t] = 0.f;
    CP_WAIT(0);
    __syncthreads();

    // ---- Phase 1: preds2*log2e = loc @ (W2*log2e)^T ----
    uint32_t pc[2][2][4][2];
#pragma unroll
    for (int p = 0; p < 2; ++p)
#pragma unroll
        for (int mi = 0; mi < 2; ++mi)
#pragma unroll
            for (int ni = 0; ni < 4; ++ni) { pc[p][mi][ni][0] = 0u; pc[p][mi][ni][1] = 0u; }

#pragma unroll 1
    for (int p = 0; p < 2; ++p) {
        const uint32_t sbB = sbase + (p ? OFF_B1 : OFF_B0);
#pragma unroll
        for (int ks = 0; ks < 8; ++ks) {
            const int k0 = ks * 16;
            uint32_t a[2][4], b[4][2];
#pragma unroll
            for (int mi = 0; mi < 2; ++mi) {
                uint32_t ad = sbA2 + (wy * 32 + mi * 16 + aRow) * SKB + (k0 + aKoff) * 2;
                LDSM4(a[mi][0], a[mi][1], a[mi][2], a[mi][3], ad);
            }
#pragma unroll
            for (int nt = 0; nt < 2; ++nt) {
                uint32_t bd = sbB + (wx * 32 + nt * 16 + bRow) * SKB + (k0 + bKoff) * 2;
                LDSM4(b[nt * 2][0], b[nt * 2][1], b[nt * 2 + 1][0], b[nt * 2 + 1][1], bd);
            }
#pragma unroll
            for (int mi = 0; mi < 2; ++mi)
#pragma unroll
                for (int ni = 0; ni < 4; ++ni) mma16h(pc[p][mi][ni], a[mi], b[ni]);
        }
    }
    __syncthreads();                      // all reads of A2 (loc) and B0/B1 (W2) done

    // overwrite A2 with preds2 (+b2*log2e); kick off pos chunks 0,1 via cp.async
#pragma unroll
    for (int p = 0; p < 2; ++p)
#pragma unroll
        for (int mi = 0; mi < 2; ++mi)
#pragma unroll
            for (int ni = 0; ni < 4; ++ni) {
                int row = wy * 32 + mi * 16 + g;
                int col = p * 64 + wx * 32 + ni * 8 + tig * 2;
                float bv0 = __ldg(b2 + col) * LOG2E, bv1 = __ldg(b2 + col + 1) * LOG2E;
                float2 lo = up2(pc[p][mi][ni][0]), hi = up2(pc[p][mi][ni][1]);
                *reinterpret_cast<uint32_t*>(sm + OFF_A2 + row * SKB + col * 2) =
                    ph2(lo.x + bv0, lo.y + bv1);
                *reinterpret_cast<uint32_t*>(sm + OFF_A2 + (row + 8) * SKB + col * 2) =
                    ph2(hi.x + bv0, hi.y + bv1);
            }
#pragma unroll
    for (int j = 0; j < 4; ++j) {         // chunk 0 -> B0
        int idx = j * 256 + t, row = idx >> 4, piece = idx & 15;
        cpa16(sbase + OFF_B0 + row * SKB + piece * 16,
              g_posh + (size_t)row * FSTRIDE + l * CDIM + piece * 8);
    }
    CP_COMMIT();
#pragma unroll
    for (int j = 0; j < 4; ++j) {         // chunk 1 -> B1
        int idx = j * 256 + t, row = idx >> 4, piece = idx & 15;
        cpa16(sbase + OFF_B1 + row * SKB + piece * 16,
              g_posh + (size_t)(64 + row) * FSTRIDE + l * CDIM + piece * 8);
    }
    CP_COMMIT();
    __syncthreads();                      // preds2 writes visible

    // ---- Phase 2: 8 pos chunks of 64, double-buffered B via cp.async ----
    float S1[4] = {0.f, 0.f, 0.f, 0.f};
    float S2[4] = {0.f, 0.f, 0.f, 0.f};
    float diagAcc = 0.f;

#pragma unroll 1
    for (int ch = 0; ch < 8; ++ch) {
        const int buf = ch & 1;
        const uint32_t sbB = sbase + (buf ? OFF_B1 : OFF_B0);
        CP_WAIT(1);                       // chunk ch landed
        __syncthreads();

        uint32_t c1[2][4][2], c2[2][4][2];
#pragma unroll
        for (int mi = 0; mi < 2; ++mi)
#pragma unroll
            for (int ni = 0; ni < 4; ++ni) {
                c1[mi][ni][0] = 0u; c1[mi][ni][1] = 0u;
                c2[mi][ni][0] = 0u; c2[mi][ni][1] = 0u;
            }

#pragma unroll
        for (int ks = 0; ks < 8; ++ks) {
            const int k0 = ks * 16;
            uint32_t a1f[2][4], a2f[2][4], b[4][2];
#pragma unroll
            for (int mi = 0; mi < 2; ++mi) {
                uint32_t off = (wy * 32 + mi * 16 + aRow) * SKB + (k0 + aKoff) * 2;
                LDSM4(a1f[mi][0], a1f[mi][1], a1f[mi][2], a1f[mi][3], sbA1 + off);
                LDSM4(a2f[mi][0], a2f[mi][1], a2f[mi][2], a2f[mi][3], sbA2 + off);
            }
#pragma unroll
            for (int nt = 0; nt < 2; ++nt) {
                uint32_t bd = sbB + (wx * 32 + nt * 16 + bRow) * SKB + (k0 + bKoff) * 2;
                LDSM4(b[nt * 2][0], b[nt * 2][1], b[nt * 2 + 1][0], b[nt * 2 + 1][1], bd);
            }
#pragma unroll
            for (int mi = 0; mi < 2; ++mi)
#pragma unroll
                for (int ni = 0; ni < 4; ++ni) {
                    mma16h(c1[mi][ni], a1f[mi], b[ni]);
                    mma16h(c2[mi][ni], a2f[mi], b[ni]);
                }
        }
        __syncthreads();                  // all warps done reading B[buf]

        if (ch < 6) {                     // chunk ch+2 -> B[buf]
#pragma unroll
            for (int j = 0; j < 4; ++j) {
                int idx = j * 256 + t, row = idx >> 4, piece = idx & 15;
                cpa16(sbB + row * SKB + piece * 16,
                      g_posh + (size_t)((ch + 2) * 64 + row) * FSTRIDE + l * CDIM + piece * 8);
            }
        }
        CP_COMMIT();                      // empty group for ch>=6 keeps FIFO count

        // epilogue: logits log2-scaled -> raw ex2
#pragma unroll
        for (int mi = 0; mi < 2; ++mi) {
            const int r0 = nb * 128 + wy * 32 + mi * 16 + g;
            const int r1 = r0 + 8;
#pragma unroll
            for (int ni = 0; ni < 4; ++ni) {
                const int col = ch * 64 + wx * 32 + ni * 8 + tig * 2;
                float2 v1lo = up2(c1[mi][ni][0]), v1hi = up2(c1[mi][ni][1]);
                float2 v2lo = up2(c2[mi][ni][0]), v2hi = up2(c2[mi][ni][1]);
                S1[mi * 2 + 0] += ex2f(v1lo.x) + ex2f(v1lo.y);
                S1[mi * 2 + 1] += ex2f(v1hi.x) + ex2f(v1hi.y);
                S2[mi * 2 + 0] += ex2f(v2lo.x) + ex2f(v2lo.y);
                S2[mi * 2 + 1] += ex2f(v2hi.x) + ex2f(v2hi.y);
                if (col     == r0) diagAcc += v1lo.x + v2lo.x;
                if (col + 1 == r0) diagAcc += v1lo.y + v2lo.y;
                if (col     == r1) diagAcc += v1hi.x + v2hi.x;
                if (col + 1 == r1) diagAcc += v1hi.y + v2hi.y;
            }
        }
    }

    // ---- Phase 3: reductions + fused finalize ----
#pragma unroll
    for (int slot = 0; slot < 4; ++slot) {
        float s1 = S1[slot], s2 = S2[slot];
        s1 += __shfl_xor_sync(0xffffffffu, s1, 1);
        s1 += __shfl_xor_sync(0xffffffffu, s1, 2);
        s2 += __shfl_xor_sync(0xffffffffu, s2, 1);
        s2 += __shfl_xor_sync(0xffffffffu, s2, 2);
        if (tig == 0) {
            int row = wy * 32 + (slot >> 1) * 16 + g + (slot & 1) * 8;
            atomicAdd(&rowS[row], s1);
            atomicAdd(&rowS[128 + row], s2);
        }
    }
    __syncthreads();

    float contrib = -diagAcc * LN2 + __logf(rowS[t]);
#pragma unroll
    for (int off = 16; off > 0; off >>= 1)
        contrib += __shfl_down_sync(0xffffffffu, contrib, off);
    if (lane == 0) wred[warp] = contrib;
    __syncthreads();
    if (t == 0) {
        float v = 0.f;
#pragma unroll
        for (int w = 0; w < 8; ++w) v += wred[w];
        atomicAdd(&g_acc, (double)v);
        __threadfence();
        unsigned fin = atomicAdd(&g_done, 1u);
        if (fin == (unsigned)(4 * LLOC - 1)) {
            out[0] = (float)(g_acc / (double)(LLOC * NTOK));
            g_done = 0;
            g_acc = 0.0;
        }
    }
}

extern "C" void kernel_launch(void* const* d_in, const int* in_sizes, int n_in,
                              void* d_out, int out_size) {
    const float* f_t      = (const float*)d_in[0];
    const float* fmap_t   = (const float*)d_in[1];
    const float* fmap_tp1 = (const float*)d_in[2];
    const float* W1       = (const float*)d_in[3];
    const float* b1       = (const float*)d_in[4];
    const float* W2       = (const float*)d_in[5];
    const float* b2       = (const float*)d_in[6];
    float* out = (float*)d_out;

    cudaFuncSetAttribute(setup_k, cudaFuncAttributeMaxDynamicSharedMemorySize, P_SMEM);
    cudaFuncSetAttribute(main_k, cudaFuncAttributeMaxDynamicSharedMemorySize, SMEM_TOTAL);

    setup_k<<<8 + CONVB, 256, P_SMEM>>>(f_t, W1, b1, fmap_tp1);
    dim3 grid(NTOK / 128, LLOC);         // (4, 144)
    main_k<<<grid, 256, SMEM_TOTAL>>>(fmap_t, W2, b2, out);
}